// round 1
// baseline (speedup 1.0000x reference)
#include <cuda_runtime.h>
#include <math.h>

#define BB 128
#define LATENT 64
#define HIDDEN 512
#define CANVAS 28
#define NPATH 2
#define SEG 3
#define NPTS 10          // points per path
#define TSAMP 32
#define MPTS (SEG*TSAMP) // 96 curve samples per path

// output offsets (floats), concat in return order
#define OFF_REND 0
#define OFF_MU   (BB*784)
#define OFF_LV   (OFF_MU + BB*64)
#define OFF_CP   (OFF_LV + BB*64)
#define OFF_W    (OFF_CP + BB*48)
#define OFF_A    (OFF_W + BB*2)

// scratch
__device__ float g_h1[BB*256];
__device__ float g_h2[BB*256];
__device__ float g_z[BB*LATENT];
__device__ float g_dh1[BB*HIDDEN];
__device__ float g_dh2[BB*HIDDEN];
__device__ float g_curve[BB*NPATH*MPTS*2];
__device__ float g_wa[BB*4]; // widths[2], alphas[2]

// ---------------- tiled GEMM + bias + activation ----------------
// ACT: 0 = none, 1 = leaky(0.2), 2 = selu
template<int ACT>
__global__ void gemm_kernel(const float* __restrict__ A, const float* __restrict__ W,
                            const float* __restrict__ bias, float* __restrict__ C,
                            int M, int N, int K) {
    __shared__ float As[16][16];
    __shared__ float Ws[16][17];
    int tx = threadIdx.x, ty = threadIdx.y;
    int row = blockIdx.y * 16 + ty;
    int col = blockIdx.x * 16 + tx;
    float acc = 0.f;
    for (int k0 = 0; k0 < K; k0 += 16) {
        As[ty][tx] = (row < M && (k0 + tx) < K) ? A[row * K + k0 + tx] : 0.f;
        Ws[ty][tx] = ((k0 + ty) < K && col < N) ? W[(k0 + ty) * N + col] : 0.f;
        __syncthreads();
#pragma unroll
        for (int kk = 0; kk < 16; kk++) acc = fmaf(As[ty][kk], Ws[kk][tx], acc);
        __syncthreads();
    }
    if (row < M && col < N) {
        acc += bias[col];
        if (ACT == 1) {
            acc = (acc >= 0.f) ? acc : 0.2f * acc;
        } else if (ACT == 2) {
            const float sc = 1.0507009873554805f, al = 1.6732632423543772f;
            acc = (acc > 0.f) ? sc * acc : sc * al * expm1f(acc);
        }
        C[row * N + col] = acc;
    }
}

// ---------------- reparameterization ----------------
__global__ void z_kernel(const float* __restrict__ eps, const float* __restrict__ out) {
    int i = blockIdx.x * 256 + threadIdx.x;
    if (i < BB * LATENT) {
        float mu = out[OFF_MU + i];
        float lv = out[OFF_LV + i];
        g_z[i] = mu + eps[i] * expf(0.5f * lv);
    }
}

// ---------------- decoder heads + bezier sampling ----------------
__global__ void heads_kernel(const float* __restrict__ pw, const float* __restrict__ pb,
                             const float* __restrict__ wdw, const float* __restrict__ wdb,
                             const float* __restrict__ aw, const float* __restrict__ ab,
                             float* __restrict__ out) {
    int b = blockIdx.x;
    int t = threadIdx.x; // 128 threads
    __shared__ float h[HIDDEN];
    __shared__ float pts[40];
    __shared__ float wa[4];
    for (int i = t; i < HIDDEN; i += 128) h[i] = g_dh2[b * HIDDEN + i];
    __syncthreads();
    if (t < 40) {
        float acc = pb[t];
        for (int k = 0; k < HIDDEN; k++) acc = fmaf(h[k], pw[k * 40 + t], acc);
        pts[t] = tanhf(acc) * 12.f + 14.f;   // *(CANVAS/2 - MARGIN) + CANVAS/2
    } else if (t < 42) {
        int j = t - 40;
        float acc = wdb[j];
        for (int k = 0; k < HIDDEN; k++) acc = fmaf(h[k], wdw[k * 2 + j], acc);
        wa[j] = 2.f / (1.f + expf(-acc)) + 1.f;  // sigmoid*2+1
    } else if (t < 44) {
        int j = t - 42;
        float acc = ab[j];
        for (int k = 0; k < HIDDEN; k++) acc = fmaf(h[k], aw[k * 2 + j], acc);
        wa[2 + j] = 1.f / (1.f + expf(-acc));
    }
    __syncthreads();
    // cp out: [P,S,4,2] from overlapping segments
    if (t < 48) {
        int p = t / 24, rem = t % 24;
        int s = rem / 8, kc = rem % 8;
        int k = kc / 2, c = kc & 1;
        out[OFF_CP + b * 48 + t] = pts[p * 20 + (3 * s + k) * 2 + c];
    }
    if (t < 4) {
        g_wa[b * 4 + t] = wa[t];
        if (t < 2) out[OFF_W + b * 2 + t] = wa[t];
        else       out[OFF_A + b * 2 + (t - 2)] = wa[t];
    }
    // curve samples: [P, S*T, 2]
    for (int i = t; i < NPATH * MPTS * 2; i += 128) {
        int p = i / (MPTS * 2);
        int m = (i / 2) % MPTS;
        int c = i & 1;
        int s = m / TSAMP, tt = m % TSAMP;
        float tv = ((float)tt + 0.5f) / (float)TSAMP;
        float u = 1.f - tv;
        float b0 = u * u * u;
        float b1 = 3.f * tv * u * u;
        float b2 = 3.f * tv * tv * u;
        float b3 = tv * tv * tv;
        const float* Pp = &pts[p * 20 + (3 * s) * 2 + c];
        float v = b0 * Pp[0] + b1 * Pp[2] + b2 * Pp[4] + b3 * Pp[6];
        g_curve[b * (NPATH * MPTS * 2) + i] = v;
    }
}

// ---------------- supersampled stroke rasterizer ----------------
__global__ void render_kernel(float* __restrict__ out) {
    int b = blockIdx.x;
    int t = threadIdx.x; // 256
    __shared__ float cux[NPATH][MPTS], cuy[NPATH][MPTS];
    __shared__ float sw[NPATH], sa[NPATH];
    for (int i = t; i < NPATH * MPTS; i += 256) {
        int p = i / MPTS, m = i % MPTS;
        cux[p][m] = g_curve[b * (NPATH * MPTS * 2) + (p * MPTS + m) * 2 + 0];
        cuy[p][m] = g_curve[b * (NPATH * MPTS * 2) + (p * MPTS + m) * 2 + 1];
    }
    if (t < 2)  sw[t] = g_wa[b * 4 + t];
    if (t >= 2 && t < 4) sa[t - 2] = g_wa[b * 4 + t];
    __syncthreads();
    for (int pix = t; pix < 784; pix += 256) {
        int py = pix / 28, px = pix % 28;
        // supersample coords: (2*p + s + 0.5)/2 = p + (s+0.5)/2
        float x0 = (float)px + 0.25f, x1 = (float)px + 0.75f;
        float y0 = (float)py + 0.25f, y1 = (float)py + 0.75f;
        float v00 = 1.f, v01 = 1.f, v10 = 1.f, v11 = 1.f;
#pragma unroll
        for (int p = 0; p < NPATH; p++) {
            float m00 = 1e30f, m01 = 1e30f, m10 = 1e30f, m11 = 1e30f;
#pragma unroll 8
            for (int m = 0; m < MPTS; m++) {
                float cx = cux[p][m], cy = cuy[p][m];
                float dx0 = x0 - cx, dx1 = x1 - cx;
                float dy0 = y0 - cy, dy1 = y1 - cy;
                float dx0s = dx0 * dx0, dx1s = dx1 * dx1;
                float dy0s = dy0 * dy0, dy1s = dy1 * dy1;
                m00 = fminf(m00, dx0s + dy0s);
                m01 = fminf(m01, dx1s + dy0s);
                m10 = fminf(m10, dx0s + dy1s);
                m11 = fminf(m11, dx1s + dy1s);
            }
            float w = sw[p] * 0.5f;
            float al = sa[p];
            float d00 = sqrtf(m00 + 1e-12f);
            float d01 = sqrtf(m01 + 1e-12f);
            float d10 = sqrtf(m10 + 1e-12f);
            float d11 = sqrtf(m11 + 1e-12f);
            // cov = sigmoid((w - d)/0.5) ; a = alpha*cov ; val *= (1-a)
            v00 *= 1.f - al / (1.f + expf((d00 - w) * 2.f));
            v01 *= 1.f - al / (1.f + expf((d01 - w) * 2.f));
            v10 *= 1.f - al / (1.f + expf((d10 - w) * 2.f));
            v11 *= 1.f - al / (1.f + expf((d11 - w) * 2.f));
        }
        out[OFF_REND + b * 784 + pix] = 1.f - 0.25f * (v00 + v01 + v10 + v11);
    }
}

extern "C" void kernel_launch(void* const* d_in, const int* in_sizes, int n_in,
                              void* d_out, int out_size) {
    const float* x    = (const float*)d_in[0];
    const float* eps  = (const float*)d_in[1];
    const float* e_w1 = (const float*)d_in[2];
    const float* e_b1 = (const float*)d_in[3];
    const float* e_w2 = (const float*)d_in[4];
    const float* e_b2 = (const float*)d_in[5];
    const float* w_mu = (const float*)d_in[6];
    const float* b_mu = (const float*)d_in[7];
    const float* w_lv = (const float*)d_in[8];
    const float* b_lv = (const float*)d_in[9];
    const float* d_w1 = (const float*)d_in[10];
    const float* d_b1 = (const float*)d_in[11];
    const float* d_w2 = (const float*)d_in[12];
    const float* d_b2 = (const float*)d_in[13];
    const float* p_w  = (const float*)d_in[14];
    const float* p_b  = (const float*)d_in[15];
    const float* wd_w = (const float*)d_in[16];
    const float* wd_b = (const float*)d_in[17];
    const float* a_w  = (const float*)d_in[18];
    const float* a_b  = (const float*)d_in[19];
    float* out = (float*)d_out;

    dim3 blk(16, 16);
    // encoder
    float* h1; cudaGetSymbolAddress((void**)&h1, g_h1);
    float* h2; cudaGetSymbolAddress((void**)&h2, g_h2);
    float* z;  cudaGetSymbolAddress((void**)&z, g_z);
    float* dh1; cudaGetSymbolAddress((void**)&dh1, g_dh1);
    float* dh2; cudaGetSymbolAddress((void**)&dh2, g_dh2);

    gemm_kernel<1><<<dim3(16, 8), blk>>>(x, e_w1, e_b1, h1, BB, 256, 784);
    gemm_kernel<1><<<dim3(16, 8), blk>>>(h1, e_w2, e_b2, h2, BB, 256, 256);
    gemm_kernel<0><<<dim3(4, 8), blk>>>(h2, w_mu, b_mu, out + OFF_MU, BB, 64, 256);
    gemm_kernel<0><<<dim3(4, 8), blk>>>(h2, w_lv, b_lv, out + OFF_LV, BB, 64, 256);
    z_kernel<<<(BB * LATENT + 255) / 256, 256>>>(eps, out);
    gemm_kernel<2><<<dim3(32, 8), blk>>>(z, d_w1, d_b1, dh1, BB, HIDDEN, LATENT);
    gemm_kernel<2><<<dim3(32, 8), blk>>>(dh1, d_w2, d_b2, dh2, BB, HIDDEN, HIDDEN);
    heads_kernel<<<BB, 128>>>(p_w, p_b, wd_w, wd_b, a_w, a_b, out);
    render_kernel<<<BB, 256>>>(out);
}

// round 2
// speedup vs baseline: 1.0723x; 1.0723x over previous
#include <cuda_runtime.h>
#include <math.h>

#define BB 128
#define NBLK 128
#define LATENT 64
#define HIDDEN 512
#define NPATH 2
#define SEG 3
#define TSAMP 32
#define MPTS (SEG*TSAMP) // 96

// output offsets (floats), concat in return order
#define OFF_REND 0
#define OFF_MU   (BB*784)
#define OFF_LV   (OFF_MU + BB*64)
#define OFF_CP   (OFF_LV + BB*64)
#define OFF_W    (OFF_CP + BB*48)
#define OFF_A    (OFF_W + BB*2)

// scratch (inter-phase activations)
__device__ float g_h1[BB*256];
__device__ float g_h2[BB*256];
__device__ float g_z[BB*LATENT];
__device__ float g_dh1[BB*HIDDEN];
__device__ float g_dh2[BB*HIDDEN];
__device__ unsigned g_cnt;   // zero-init; last arriver resets to 0 each barrier
__device__ unsigned g_gen;   // monotonically increasing across barriers/replays

__device__ __forceinline__ void grid_sync() {
    __syncthreads();
    if (threadIdx.x == 0) {
        __threadfence();                       // publish this CTA's writes
        volatile unsigned* vgen = &g_gen;
        unsigned gen = *vgen;                  // read BEFORE arrival (race-free: gen
                                               // can't advance until we arrive)
        if (atomicAdd(&g_cnt, 1u) == NBLK - 1) {
            g_cnt = 0;
            __threadfence();
            atomicAdd(&g_gen, 1u);
        } else {
            while (*vgen == gen) { }
        }
    }
    __syncthreads();
}

// ---- tiled GEMM phase over persistent grid. M = BB. ACT: 0 none, 1 leaky, 2 selu
template<int ACT>
__device__ void gemm_phase(const float* __restrict__ A, const float* __restrict__ W,
                           const float* __restrict__ bias, float* __restrict__ C,
                           int N, int K, float* sm) {
    float (*As)[16] = (float(*)[16])sm;
    float (*Ws)[17] = (float(*)[17])(sm + 256);
    int tx = threadIdx.x & 15, ty = threadIdx.x >> 4;
    int tpr = N >> 4;
    int tiles = (BB >> 4) * tpr;
    for (int tile = blockIdx.x; tile < tiles; tile += NBLK) {
        int mb = tile / tpr, nb = tile - mb * tpr;
        int row = mb * 16 + ty, col = nb * 16 + tx;
        float acc = 0.f;
        for (int k0 = 0; k0 < K; k0 += 16) {
            As[ty][tx] = __ldcg(&A[row * K + k0 + tx]);
            Ws[ty][tx] = W[(k0 + ty) * N + col];
            __syncthreads();
#pragma unroll
            for (int kk = 0; kk < 16; kk++) acc = fmaf(As[ty][kk], Ws[kk][tx], acc);
            __syncthreads();
        }
        acc += bias[col];
        if (ACT == 1) {
            acc = (acc >= 0.f) ? acc : 0.2f * acc;
        } else if (ACT == 2) {
            const float sc = 1.0507009873554805f, al = 1.6732632423543772f;
            acc = (acc > 0.f) ? sc * acc : sc * al * expm1f(acc);
        }
        C[row * N + col] = acc;
    }
}

__global__ void __launch_bounds__(256, 1)
mega_kernel(const float* __restrict__ x,    const float* __restrict__ eps,
            const float* __restrict__ e_w1, const float* __restrict__ e_b1,
            const float* __restrict__ e_w2, const float* __restrict__ e_b2,
            const float* __restrict__ w_mu, const float* __restrict__ b_mu,
            const float* __restrict__ w_lv, const float* __restrict__ b_lv,
            const float* __restrict__ d_w1, const float* __restrict__ d_b1,
            const float* __restrict__ d_w2, const float* __restrict__ d_b2,
            const float* __restrict__ p_w,  const float* __restrict__ p_b,
            const float* __restrict__ wd_w, const float* __restrict__ wd_b,
            const float* __restrict__ a_w,  const float* __restrict__ a_b,
            float* __restrict__ out) {
    __shared__ float sm[960];
    int t = threadIdx.x;

    // ---- P0: encoder layer1: [128,784]@[784,256] leaky
    gemm_phase<1>(x, e_w1, e_b1, g_h1, 256, 784, sm);
    grid_sync();
    // ---- P1: encoder layer2: [128,256]@[256,256] leaky
    gemm_phase<1>(g_h1, e_w2, e_b2, g_h2, 256, 256, sm);
    grid_sync();
    // ---- P2: mu + logvar + z fused  (tiles over [128 x 64])
    {
        float (*As)[16] = (float(*)[16])sm;
        float (*Wm)[17] = (float(*)[17])(sm + 256);
        float (*Wl)[17] = (float(*)[17])(sm + 528);
        int tx = t & 15, ty = t >> 4;
        for (int tile = blockIdx.x; tile < 32; tile += NBLK) {
            int mb = tile >> 2, nb = tile & 3;
            int row = mb * 16 + ty, col = nb * 16 + tx;
            float am = 0.f, av = 0.f;
            for (int k0 = 0; k0 < 256; k0 += 16) {
                As[ty][tx] = __ldcg(&g_h2[row * 256 + k0 + tx]);
                Wm[ty][tx] = w_mu[(k0 + ty) * 64 + col];
                Wl[ty][tx] = w_lv[(k0 + ty) * 64 + col];
                __syncthreads();
#pragma unroll
                for (int kk = 0; kk < 16; kk++) {
                    float a = As[ty][kk];
                    am = fmaf(a, Wm[kk][tx], am);
                    av = fmaf(a, Wl[kk][tx], av);
                }
                __syncthreads();
            }
            am += b_mu[col]; av += b_lv[col];
            out[OFF_MU + row * 64 + col] = am;
            out[OFF_LV + row * 64 + col] = av;
            g_z[row * 64 + col] = am + eps[row * 64 + col] * expf(0.5f * av);
        }
    }
    grid_sync();
    // ---- P3: decoder layer1: [128,64]@[64,512] selu
    gemm_phase<2>(g_z, d_w1, d_b1, g_dh1, 512, 64, sm);
    grid_sync();
    // ---- P4: decoder layer2: [128,512]@[512,512] selu
    gemm_phase<2>(g_dh1, d_w2, d_b2, g_dh2, 512, 512, sm);
    grid_sync();
    // ---- P5: heads + bezier + render, one CTA per batch element
    {
        int b = blockIdx.x;
        float* h   = sm;        // 512
        float* pts = sm + 512;  // 40
        float* wa  = sm + 552;  // 4
        float* cux = sm + 556;  // 192 (2 paths x 96)
        float* cuy = sm + 748;  // 192
        for (int i = t; i < HIDDEN; i += 256) h[i] = __ldcg(&g_dh2[b * HIDDEN + i]);
        __syncthreads();
        if (t < 40) {
            float acc = p_b[t];
            for (int k = 0; k < HIDDEN; k++) acc = fmaf(h[k], p_w[k * 40 + t], acc);
            pts[t] = tanhf(acc) * 12.f + 14.f;
        } else if (t < 42) {
            int j = t - 40;
            float acc = wd_b[j];
            for (int k = 0; k < HIDDEN; k++) acc = fmaf(h[k], wd_w[k * 2 + j], acc);
            wa[j] = 2.f / (1.f + __expf(-acc)) + 1.f;
        } else if (t < 44) {
            int j = t - 42;
            float acc = a_b[j];
            for (int k = 0; k < HIDDEN; k++) acc = fmaf(h[k], a_w[k * 2 + j], acc);
            wa[2 + j] = 1.f / (1.f + __expf(-acc));
        }
        __syncthreads();
        // cp out: [P,S,4,2] overlapping segments
        if (t < 48) {
            int p = t / 24, rem = t % 24;
            int s = rem / 8, kc = rem % 8;
            int k = kc / 2, c = kc & 1;
            out[OFF_CP + b * 48 + t] = pts[p * 20 + (3 * s + k) * 2 + c];
        }
        if (t < 2)            out[OFF_W + b * 2 + t] = wa[t];
        if (t >= 2 && t < 4)  out[OFF_A + b * 2 + (t - 2)] = wa[t];
        // curve samples into smem
        for (int i = t; i < NPATH * MPTS * 2; i += 256) {
            int p = i / (MPTS * 2);
            int m = (i >> 1) % MPTS;
            int c = i & 1;
            int s = m / TSAMP, tt = m % TSAMP;
            float tv = ((float)tt + 0.5f) / (float)TSAMP;
            float u = 1.f - tv;
            float b0 = u * u * u;
            float b1 = 3.f * tv * u * u;
            float b2 = 3.f * tv * tv * u;
            float b3 = tv * tv * tv;
            const float* Pp = &pts[p * 20 + (3 * s) * 2 + c];
            float v = b0 * Pp[0] + b1 * Pp[2] + b2 * Pp[4] + b3 * Pp[6];
            (c ? cuy : cux)[p * MPTS + m] = v;
        }
        __syncthreads();
        // supersampled rasterizer: 4 subsamples tracked per curve point
        for (int pix = t; pix < 784; pix += 256) {
            int py = pix / 28, px = pix % 28;
            float x0 = (float)px + 0.25f, x1 = (float)px + 0.75f;
            float y0 = (float)py + 0.25f, y1 = (float)py + 0.75f;
            float v00 = 1.f, v01 = 1.f, v10 = 1.f, v11 = 1.f;
#pragma unroll
            for (int p = 0; p < NPATH; p++) {
                float m00 = 1e30f, m01 = 1e30f, m10 = 1e30f, m11 = 1e30f;
#pragma unroll 8
                for (int m = 0; m < MPTS; m++) {
                    float cx = cux[p * MPTS + m], cy = cuy[p * MPTS + m];
                    float dx0 = x0 - cx, dx1 = x1 - cx;
                    float dy0 = y0 - cy, dy1 = y1 - cy;
                    float dx0s = dx0 * dx0, dx1s = dx1 * dx1;
                    float dy0s = dy0 * dy0, dy1s = dy1 * dy1;
                    m00 = fminf(m00, dx0s + dy0s);
                    m01 = fminf(m01, dx1s + dy0s);
                    m10 = fminf(m10, dx0s + dy1s);
                    m11 = fminf(m11, dx1s + dy1s);
                }
                float w = wa[p] * 0.5f;
                float al = wa[2 + p];
                float d00 = sqrtf(m00 + 1e-12f);
                float d01 = sqrtf(m01 + 1e-12f);
                float d10 = sqrtf(m10 + 1e-12f);
                float d11 = sqrtf(m11 + 1e-12f);
                v00 *= 1.f - al / (1.f + __expf((d00 - w) * 2.f));
                v01 *= 1.f - al / (1.f + __expf((d01 - w) * 2.f));
                v10 *= 1.f - al / (1.f + __expf((d10 - w) * 2.f));
                v11 *= 1.f - al / (1.f + __expf((d11 - w) * 2.f));
            }
            out[OFF_REND + b * 784 + pix] = 1.f - 0.25f * (v00 + v01 + v10 + v11);
        }
    }
}

extern "C" void kernel_launch(void* const* d_in, const int* in_sizes, int n_in,
                              void* d_out, int out_size) {
    const float* x    = (const float*)d_in[0];
    const float* eps  = (const float*)d_in[1];
    const float* e_w1 = (const float*)d_in[2];
    const float* e_b1 = (const float*)d_in[3];
    const float* e_w2 = (const float*)d_in[4];
    const float* e_b2 = (const float*)d_in[5];
    const float* w_mu = (const float*)d_in[6];
    const float* b_mu = (const float*)d_in[7];
    const float* w_lv = (const float*)d_in[8];
    const float* b_lv = (const float*)d_in[9];
    const float* d_w1 = (const float*)d_in[10];
    const float* d_b1 = (const float*)d_in[11];
    const float* d_w2 = (const float*)d_in[12];
    const float* d_b2 = (const float*)d_in[13];
    const float* p_w  = (const float*)d_in[14];
    const float* p_b  = (const float*)d_in[15];
    const float* wd_w = (const float*)d_in[16];
    const float* wd_b = (const float*)d_in[17];
    const float* a_w  = (const float*)d_in[18];
    const float* a_b  = (const float*)d_in[19];
    float* out = (float*)d_out;

    mega_kernel<<<NBLK, 256>>>(x, eps, e_w1, e_b1, e_w2, e_b2, w_mu, b_mu,
                               w_lv, b_lv, d_w1, d_b1, d_w2, d_b2,
                               p_w, p_b, wd_w, wd_b, a_w, a_b, out);
}

// round 4
// speedup vs baseline: 1.5493x; 1.4448x over previous
#include <cuda_runtime.h>
#include <math.h>

#define BB 128
#define NBLK 128
#define NTHR 512
#define LATENT 64
#define HIDDEN 512
#define NPATH 2
#define SEG 3
#define TSAMP 32
#define MPTS (SEG*TSAMP) // 96

// output offsets (floats), concat in return order
#define OFF_REND 0
#define OFF_MU   (BB*784)
#define OFF_LV   (OFF_MU + BB*64)
#define OFF_CP   (OFF_LV + BB*64)
#define OFF_W    (OFF_CP + BB*48)
#define OFF_A    (OFF_W + BB*2)

// packed fp32x2 (Blackwell)
#define F32X2_ADD(o,a,b)   asm("add.rn.f32x2 %0,%1,%2;" : "=l"(o) : "l"(a), "l"(b))
#define F32X2_MUL(o,a,b)   asm("mul.rn.f32x2 %0,%1,%2;" : "=l"(o) : "l"(a), "l"(b))
#define F32X2_FMA(o,a,b,c) asm("fma.rn.f32x2 %0,%1,%2,%3;" : "=l"(o) : "l"(a), "l"(b), "l"(c))
#define PACK2(o,lo,hi)     asm("mov.b64 %0,{%1,%2};" : "=l"(o) : "r"(lo), "r"(hi))
#define UNPACK2(lo,hi,i)   asm("mov.b64 {%0,%1},%2;" : "=r"(lo), "=r"(hi) : "l"(i))

// scratch (inter-phase activations)
__device__ float g_h1[BB*256];
__device__ float g_h2[BB*256];
__device__ float g_z[BB*LATENT];
__device__ float g_dh1[BB*HIDDEN];
__device__ float g_dh2[BB*HIDDEN];
__device__ unsigned g_cnt;   // zero-init; last arriver resets each barrier
__device__ unsigned g_gen;   // monotonically increasing

__device__ __forceinline__ void grid_sync() {
    __syncthreads();
    if (threadIdx.x == 0) {
        __threadfence();
        volatile unsigned* vgen = &g_gen;
        unsigned gen = *vgen;  // read BEFORE arrival
        if (atomicAdd(&g_cnt, 1u) == NBLK - 1) {
            g_cnt = 0;
            __threadfence();
            atomicAdd(&g_gen, 1u);
        } else {
            while (*vgen == gen) { __nanosleep(32); }
        }
    }
    __syncthreads();
}

// ---- tiled GEMM phase, 512 threads: K split across two 256-thread halves.
// M = BB, dims multiples of 16. ACT: 0 none, 1 leaky, 2 selu
template<int ACT>
__device__ void gemm_phase(const float* __restrict__ A, const float* __restrict__ W,
                           const float* __restrict__ bias, float* __restrict__ C,
                           int N, int K, float* sm) {
    float (*As)[16][16] = (float(*)[16][16])sm;          // [2][16][16]
    float (*Ws)[16][17] = (float(*)[16][17])(sm + 512);  // [2][16][17]
    float* Cpart = sm + 512 + 544;                       // 256
    int t = threadIdx.x;
    int kh = t >> 8, tid = t & 255;
    int tx = tid & 15, ty = tid >> 4;
    int Kt = K >> 4;
    int Kt0 = (Kt + 1) >> 1;
    int kbeg = kh ? Kt0 : 0;
    int kend = kh ? Kt : Kt0;
    int tpr = N >> 4;
    int tiles = (BB >> 4) * tpr;
    for (int tile = blockIdx.x; tile < tiles; tile += NBLK) {
        int mb = tile / tpr, nb = tile - mb * tpr;
        int row = mb * 16 + ty, col = nb * 16 + tx;
        float acc = 0.f;
        for (int i = 0; i < Kt0; i++) {
            int kt = kbeg + i;
            bool ok = kt < kend;
            if (ok) {
                int k0 = kt << 4;
                As[kh][ty][tx] = __ldcg(&A[row * K + k0 + tx]);
                Ws[kh][ty][tx] = W[(k0 + ty) * N + col];
            }
            __syncthreads();
            if (ok) {
#pragma unroll
                for (int kk = 0; kk < 16; kk++)
                    acc = fmaf(As[kh][ty][kk], Ws[kh][kk][tx], acc);
            }
            __syncthreads();
        }
        if (kh == 1) Cpart[tid] = acc;
        __syncthreads();
        if (kh == 0) {
            acc += Cpart[tid] + bias[col];
            if (ACT == 1) {
                acc = (acc >= 0.f) ? acc : 0.2f * acc;
            } else if (ACT == 2) {
                const float sc = 1.0507009873554805f, al = 1.6732632423543772f;
                acc = (acc > 0.f) ? sc * acc : sc * al * expm1f(acc);
            }
            C[row * N + col] = acc;
        }
        __syncthreads();
    }
}

__global__ void __launch_bounds__(NTHR, 1)
mega_kernel(const float* __restrict__ x,    const float* __restrict__ eps,
            const float* __restrict__ e_w1, const float* __restrict__ e_b1,
            const float* __restrict__ e_w2, const float* __restrict__ e_b2,
            const float* __restrict__ w_mu, const float* __restrict__ b_mu,
            const float* __restrict__ w_lv, const float* __restrict__ b_lv,
            const float* __restrict__ d_w1, const float* __restrict__ d_b1,
            const float* __restrict__ d_w2, const float* __restrict__ d_b2,
            const float* __restrict__ p_w,  const float* __restrict__ p_b,
            const float* __restrict__ wd_w, const float* __restrict__ wd_b,
            const float* __restrict__ a_w,  const float* __restrict__ a_b,
            float* __restrict__ out) {
    __shared__ __align__(16) float sm[2200];
    int t = threadIdx.x;

    // P0: enc1 [128,784]@[784,256] leaky
    gemm_phase<1>(x, e_w1, e_b1, g_h1, 256, 784, sm);
    grid_sync();
    // P1: enc2 [128,256]@[256,256] leaky
    gemm_phase<1>(g_h1, e_w2, e_b2, g_h2, 256, 256, sm);
    grid_sync();
    // P2: mu + logvar + z fused, K split across halves
    {
        float (*As)[16][16] = (float(*)[16][16])sm;            // [2][16][16]
        float (*Wm)[16][17] = (float(*)[16][17])(sm + 512);    // [2][16][17]
        float (*Wl)[16][17] = (float(*)[16][17])(sm + 1056);   // [2][16][17]
        float* Cm = sm + 1600;  // 256
        float* Cv = sm + 1856;  // 256
        int kh = t >> 8, tid = t & 255;
        int tx = tid & 15, ty = tid >> 4;
        for (int tile = blockIdx.x; tile < 32; tile += NBLK) {
            int mb = tile >> 2, nb = tile & 3;
            int row = mb * 16 + ty, col = nb * 16 + tx;
            float am = 0.f, av = 0.f;
            for (int i = 0; i < 8; i++) {           // 16 k-tiles, 8 per half
                int k0 = (kh * 8 + i) << 4;
                As[kh][ty][tx] = __ldcg(&g_h2[row * 256 + k0 + tx]);
                Wm[kh][ty][tx] = w_mu[(k0 + ty) * 64 + col];
                Wl[kh][ty][tx] = w_lv[(k0 + ty) * 64 + col];
                __syncthreads();
#pragma unroll
                for (int kk = 0; kk < 16; kk++) {
                    float a = As[kh][ty][kk];
                    am = fmaf(a, Wm[kh][kk][tx], am);
                    av = fmaf(a, Wl[kh][kk][tx], av);
                }
                __syncthreads();
            }
            if (kh == 1) { Cm[tid] = am; Cv[tid] = av; }
            __syncthreads();
            if (kh == 0) {
                am += Cm[tid] + b_mu[col];
                av += Cv[tid] + b_lv[col];
                out[OFF_MU + row * 64 + col] = am;
                out[OFF_LV + row * 64 + col] = av;
                g_z[row * 64 + col] = am + eps[row * 64 + col] * expf(0.5f * av);
            }
            __syncthreads();
        }
    }
    grid_sync();
    // P3: dec1 [128,64]@[64,512] selu
    gemm_phase<2>(g_z, d_w1, d_b1, g_dh1, 512, 64, sm);
    grid_sync();
    // P4: dec2 [128,512]@[512,512] selu
    gemm_phase<2>(g_dh1, d_w2, d_b2, g_dh2, 512, 512, sm);
    grid_sync();
    // P5: heads + bezier + render, one CTA per batch element
    {
        int b = blockIdx.x;
        float* h   = sm;        // 512
        float* pts = sm + 512;  // 40
        float* wa  = sm + 552;  // 4
        float* cux = sm + 556;  // 192 (8B-aligned: 556*4 % 8 == 0)
        float* cuy = sm + 748;  // 192 (8B-aligned)
        h[t] = __ldcg(&g_dh2[b * HIDDEN + t]);
        __syncthreads();
        // heads: warp per output, shfl reduce
        {
            int wid = t >> 5, lane = t & 31;
            for (int o = wid; o < 44; o += 16) {
                const float* Wp; float bias; int stride;
                if (o < 40)      { Wp = p_w + o;         stride = 40; bias = p_b[o]; }
                else if (o < 42) { Wp = wd_w + (o - 40); stride = 2;  bias = wd_b[o - 40]; }
                else             { Wp = a_w + (o - 42);  stride = 2;  bias = a_b[o - 42]; }
                float acc = 0.f;
                for (int k = lane; k < HIDDEN; k += 32)
                    acc = fmaf(h[k], Wp[k * stride], acc);
#pragma unroll
                for (int off = 16; off; off >>= 1)
                    acc += __shfl_down_sync(0xffffffffu, acc, off);
                if (lane == 0) {
                    acc += bias;
                    if (o < 40)      pts[o] = tanhf(acc) * 12.f + 14.f;
                    else if (o < 42) wa[o - 40] = 2.f / (1.f + __expf(-acc)) + 1.f;
                    else             wa[o - 40] = 1.f / (1.f + __expf(-acc));
                }
            }
        }
        __syncthreads();
        // cp out: [P,S,4,2] overlapping segments
        if (t < 48) {
            int p = t / 24, rem = t % 24;
            int s = rem / 8, kc = rem % 8;
            int k = kc / 2, c = kc & 1;
            out[OFF_CP + b * 48 + t] = pts[p * 20 + (3 * s + k) * 2 + c];
        }
        if (t < 2)            out[OFF_W + b * 2 + t] = wa[t];
        if (t >= 2 && t < 4)  out[OFF_A + b * 2 + (t - 2)] = wa[t];
        // curve samples into smem
        if (t < NPATH * MPTS * 2) {
            int i = t;
            int p = i / (MPTS * 2);
            int m = (i >> 1) % MPTS;
            int c = i & 1;
            int s = m / TSAMP, tt = m % TSAMP;
            float tv = ((float)tt + 0.5f) / (float)TSAMP;
            float u = 1.f - tv;
            float b0 = u * u * u;
            float b1 = 3.f * tv * u * u;
            float b2 = 3.f * tv * tv * u;
            float b3 = tv * tv * tv;
            const float* Pp = &pts[p * 20 + (3 * s) * 2 + c];
            float v = b0 * Pp[0] + b1 * Pp[2] + b2 * Pp[4] + b3 * Pp[6];
            (c ? cuy : cux)[p * MPTS + m] = v;
        }
        __syncthreads();
        // rasterizer: packed f32x2, 2 curve points per iteration, 4 subsamples
        for (int pix = t; pix < 784; pix += NTHR) {
            int py = pix / 28, px = pix % 28;
            float x0 = (float)px + 0.25f, x1 = (float)px + 0.75f;
            float y0 = (float)py + 0.25f, y1 = (float)py + 0.75f;
            float nx0 = -x0, nx1 = -x1, ny0 = -y0, ny1 = -y1;
            unsigned long long nx0p, nx1p, ny0p, ny1p;
            PACK2(nx0p, __float_as_uint(nx0), __float_as_uint(nx0));
            PACK2(nx1p, __float_as_uint(nx1), __float_as_uint(nx1));
            PACK2(ny0p, __float_as_uint(ny0), __float_as_uint(ny0));
            PACK2(ny1p, __float_as_uint(ny1), __float_as_uint(ny1));
            float v00 = 1.f, v01 = 1.f, v10 = 1.f, v11 = 1.f;
#pragma unroll
            for (int p = 0; p < NPATH; p++) {
                const unsigned long long* cx2 =
                    (const unsigned long long*)(cux + p * MPTS);
                const unsigned long long* cy2 =
                    (const unsigned long long*)(cuy + p * MPTS);
                float m00 = 1e30f, m01 = 1e30f, m10 = 1e30f, m11 = 1e30f;
#pragma unroll 8
                for (int i = 0; i < MPTS / 2; i++) {
                    unsigned long long cxp = cx2[i];
                    unsigned long long cyp = cy2[i];
                    unsigned long long dx0, dx1, dy0, dy1, sy0, sy1;
                    unsigned long long s00, s01, s10, s11;
                    F32X2_ADD(dx0, cxp, nx0p);
                    F32X2_ADD(dx1, cxp, nx1p);
                    F32X2_ADD(dy0, cyp, ny0p);
                    F32X2_ADD(dy1, cyp, ny1p);
                    F32X2_MUL(sy0, dy0, dy0);
                    F32X2_MUL(sy1, dy1, dy1);
                    F32X2_FMA(s00, dx0, dx0, sy0);
                    F32X2_FMA(s01, dx1, dx1, sy0);
                    F32X2_FMA(s10, dx0, dx0, sy1);
                    F32X2_FMA(s11, dx1, dx1, sy1);
                    unsigned lo, hi;
                    UNPACK2(lo, hi, s00);
                    m00 = fminf(m00, __uint_as_float(lo));
                    m00 = fminf(m00, __uint_as_float(hi));
                    UNPACK2(lo, hi, s01);
                    m01 = fminf(m01, __uint_as_float(lo));
                    m01 = fminf(m01, __uint_as_float(hi));
                    UNPACK2(lo, hi, s10);
                    m10 = fminf(m10, __uint_as_float(lo));
                    m10 = fminf(m10, __uint_as_float(hi));
                    UNPACK2(lo, hi, s11);
                    m11 = fminf(m11, __uint_as_float(lo));
                    m11 = fminf(m11, __uint_as_float(hi));
                }
                float w = wa[p] * 0.5f;
                float al = wa[2 + p];
                float d00 = sqrtf(m00 + 1e-12f);
                float d01 = sqrtf(m01 + 1e-12f);
                float d10 = sqrtf(m10 + 1e-12f);
                float d11 = sqrtf(m11 + 1e-12f);
                v00 *= 1.f - al / (1.f + __expf((d00 - w) * 2.f));
                v01 *= 1.f - al / (1.f + __expf((d01 - w) * 2.f));
                v10 *= 1.f - al / (1.f + __expf((d10 - w) * 2.f));
                v11 *= 1.f - al / (1.f + __expf((d11 - w) * 2.f));
            }
            out[OFF_REND + b * 784 + pix] = 1.f - 0.25f * (v00 + v01 + v10 + v11);
        }
    }
}

extern "C" void kernel_launch(void* const* d_in, const int* in_sizes, int n_in,
                              void* d_out, int out_size) {
    const float* x    = (const float*)d_in[0];
    const float* eps  = (const float*)d_in[1];
    const float* e_w1 = (const float*)d_in[2];
    const float* e_b1 = (const float*)d_in[3];
    const float* e_w2 = (const float*)d_in[4];
    const float* e_b2 = (const float*)d_in[5];
    const float* w_mu = (const float*)d_in[6];
    const float* b_mu = (const float*)d_in[7];
    const float* w_lv = (const float*)d_in[8];
    const float* b_lv = (const float*)d_in[9];
    const float* d_w1 = (const float*)d_in[10];
    const float* d_b1 = (const float*)d_in[11];
    const float* d_w2 = (const float*)d_in[12];
    const float* d_b2 = (const float*)d_in[13];
    const float* p_w  = (const float*)d_in[14];
    const float* p_b  = (const float*)d_in[15];
    const float* wd_w = (const float*)d_in[16];
    const float* wd_b = (const float*)d_in[17];
    const float* a_w  = (const float*)d_in[18];
    const float* a_b  = (const float*)d_in[19];
    float* out = (float*)d_out;

    mega_kernel<<<NBLK, NTHR>>>(x, eps, e_w1, e_b1, e_w2, e_b2, w_mu, b_mu,
                                w_lv, b_lv, d_w1, d_b1, d_w2, d_b2,
                                p_w, p_b, wd_w, wd_b, a_w, a_b, out);
}

// round 8
// speedup vs baseline: 1.8151x; 1.1716x over previous
#include <cuda_runtime.h>
#include <math.h>

#define BB 128
#define NBLK 128
#define NTHR 512
#define LATENT 64
#define HIDDEN 512
#define NPATH 2
#define SEG 3
#define TSAMP 32
#define MPTS (SEG*TSAMP) // 96

// output offsets (floats), concat in return order
#define OFF_REND 0
#define OFF_MU   (BB*784)
#define OFF_LV   (OFF_MU + BB*64)
#define OFF_CP   (OFF_LV + BB*64)
#define OFF_W    (OFF_CP + BB*48)
#define OFF_A    (OFF_W + BB*2)

// packed fp32x2 (Blackwell)
#define F32X2_ADD(o,a,b)   asm("add.rn.f32x2 %0,%1,%2;" : "=l"(o) : "l"(a), "l"(b))
#define F32X2_MUL(o,a,b)   asm("mul.rn.f32x2 %0,%1,%2;" : "=l"(o) : "l"(a), "l"(b))
#define F32X2_FMA(o,a,b,c) asm("fma.rn.f32x2 %0,%1,%2,%3;" : "=l"(o) : "l"(a), "l"(b), "l"(c))
#define PACK2(o,lo,hi)     asm("mov.b64 %0,{%1,%2};" : "=l"(o) : "r"(lo), "r"(hi))
#define UNPACK2(lo,hi,i)   asm("mov.b64 {%0,%1},%2;" : "=r"(lo), "=r"(hi) : "l"(i))

// scratch (inter-phase activations)
__device__ float g_h1[BB*256];
__device__ float g_h2[BB*256];
__device__ float g_z[BB*LATENT];
__device__ float g_dh1[BB*HIDDEN];
__device__ float g_dh2[BB*HIDDEN];
__device__ unsigned g_cnt;   // zero-init; last arriver resets each barrier
__device__ unsigned g_gen;   // monotonically increasing

__device__ __forceinline__ void grid_sync() {
    __syncthreads();
    if (threadIdx.x == 0) {
        __threadfence();
        volatile unsigned* vgen = &g_gen;
        unsigned gen = *vgen;  // read BEFORE arrival
        if (atomicAdd(&g_cnt, 1u) == NBLK - 1) {
            g_cnt = 0;
            __threadfence();
            atomicAdd(&g_gen, 1u);
        } else {
            while (*vgen == gen) { __nanosleep(32); }
        }
    }
    __syncthreads();
}

// ---- pipelined tiled GEMM phase, 512 threads, K split across two halves.
// Per-half DOUBLE-BUFFERED smem (buffer index = kh*2 + stage) + 2-ahead
// register prefetch, 1 bar per k-iter.
// M = BB, dims multiples of 16. ACT: 0 none, 1 leaky, 2 selu
template<int ACT>
__device__ void gemm_phase(const float* __restrict__ A, const float* __restrict__ W,
                           const float* __restrict__ bias, float* __restrict__ C,
                           int N, int K, float* sm) {
    float (*As)[16][16] = (float(*)[16][16])sm;           // [4][16][16] = 1024
    float (*Ws)[16][17] = (float(*)[16][17])(sm + 1024);  // [4][16][17] = 1088
    float* Cpart = sm + 2112;                             // 256
    int t = threadIdx.x;
    int kh = t >> 8, tid = t & 255;
    int tx = tid & 15, ty = tid >> 4;
    int Kt = K >> 4;
    int Kt0 = (Kt + 1) >> 1;        // common loop trip count
    int kbeg = kh ? Kt0 : 0;
    int nk = kh ? (Kt - Kt0) : Kt0; // this half's valid k-tiles
    int tpr = N >> 4;
    int tiles = (BB >> 4) * tpr;
    for (int tile = blockIdx.x; tile < tiles; tile += NBLK) {
        int mb = tile / tpr, nb = tile - mb * tpr;
        int row = mb * 16 + ty, col = nb * 16 + tx;
        const float* Arow = A + row * K + tx;
        const float* Wcol = W + ty * N + col;
        float ra0 = 0.f, rw0 = 0.f, ra1 = 0.f, rw1 = 0.f;
        if (0 < nk) { int k0 = kbeg << 4;
                      ra0 = __ldcg(&Arow[k0]); rw0 = __ldcg(&Wcol[(long)k0 * N]); }
        if (1 < nk) { int k0 = (kbeg + 1) << 4;
                      ra1 = __ldcg(&Arow[k0]); rw1 = __ldcg(&Wcol[(long)k0 * N]); }
        float acc = 0.f;
        for (int i = 0; i < Kt0; i++) {
            int s = (kh << 1) | (i & 1);
            bool ok = i < nk;
            if (ok) { As[s][ty][tx] = ra0; Ws[s][ty][tx] = rw0; }
            ra0 = ra1; rw0 = rw1;
            if (i + 2 < nk) { int k0 = (kbeg + i + 2) << 4;
                              ra1 = __ldcg(&Arow[k0]); rw1 = __ldcg(&Wcol[(long)k0 * N]); }
            __syncthreads();
            if (ok) {
#pragma unroll
                for (int kk = 0; kk < 16; kk++)
                    acc = fmaf(As[s][ty][kk], Ws[s][kk][tx], acc);
            }
        }
        if (kh == 1) Cpart[tid] = acc;
        __syncthreads();   // Cpart visible + all compute done
        if (kh == 0) {
            acc += Cpart[tid] + bias[col];
            if (ACT == 1) {
                acc = (acc >= 0.f) ? acc : 0.2f * acc;
            } else if (ACT == 2) {
                const float sc = 1.0507009873554805f, al = 1.6732632423543772f;
                acc = (acc > 0.f) ? sc * acc : sc * al * expm1f(acc);
            }
            C[row * N + col] = acc;
        }
        __syncthreads();   // protect smem reuse by next tile
    }
}

__global__ void __launch_bounds__(NTHR, 1)
mega_kernel(const float* __restrict__ x,    const float* __restrict__ eps,
            const float* __restrict__ e_w1, const float* __restrict__ e_b1,
            const float* __restrict__ e_w2, const float* __restrict__ e_b2,
            const float* __restrict__ w_mu, const float* __restrict__ b_mu,
            const float* __restrict__ w_lv, const float* __restrict__ b_lv,
            const float* __restrict__ d_w1, const float* __restrict__ d_b1,
            const float* __restrict__ d_w2, const float* __restrict__ d_b2,
            const float* __restrict__ p_w,  const float* __restrict__ p_b,
            const float* __restrict__ wd_w, const float* __restrict__ wd_b,
            const float* __restrict__ a_w,  const float* __restrict__ a_b,
            float* __restrict__ out) {
    __shared__ __align__(16) float sm[3720];
    int t = threadIdx.x;

    // P0: enc1 [128,784]@[784,256] leaky
    gemm_phase<1>(x, e_w1, e_b1, g_h1, 256, 784, sm);
    grid_sync();
    // P1: enc2 [128,256]@[256,256] leaky
    gemm_phase<1>(g_h1, e_w2, e_b2, g_h2, 256, 256, sm);
    grid_sync();
    // P2: mu + logvar + z fused, pipelined, per-half double buffers
    {
        float (*As)[16][16] = (float(*)[16][16])sm;            // [4][16][16] 1024
        float (*Wm)[16][17] = (float(*)[16][17])(sm + 1024);   // [4][16][17] 1088
        float (*Wl)[16][17] = (float(*)[16][17])(sm + 2112);   // [4][16][17] 1088
        float* Cm = sm + 3200;  // 256
        float* Cv = sm + 3456;  // 256
        int kh = t >> 8, tid = t & 255;
        int tx = tid & 15, ty = tid >> 4;
        const int NK = 8;       // 16 k-tiles, 8 per half
        for (int tile = blockIdx.x; tile < 32; tile += NBLK) {
            int mb = tile >> 2, nb = tile & 3;
            int row = mb * 16 + ty, col = nb * 16 + tx;
            const float* Arow = g_h2 + row * 256 + tx;
            const float* Wmc = w_mu + ty * 64 + col;
            const float* Wlc = w_lv + ty * 64 + col;
            int kb = kh * NK;
            float ra0, rm0, rl0, ra1, rm1, rl1;
            { int k0 = kb << 4;
              ra0 = __ldcg(&Arow[k0]); rm0 = __ldcg(&Wmc[k0 * 64]); rl0 = __ldcg(&Wlc[k0 * 64]); }
            { int k0 = (kb + 1) << 4;
              ra1 = __ldcg(&Arow[k0]); rm1 = __ldcg(&Wmc[k0 * 64]); rl1 = __ldcg(&Wlc[k0 * 64]); }
            float am = 0.f, av = 0.f;
            for (int i = 0; i < NK; i++) {
                int s = (kh << 1) | (i & 1);
                As[s][ty][tx] = ra0; Wm[s][ty][tx] = rm0; Wl[s][ty][tx] = rl0;
                ra0 = ra1; rm0 = rm1; rl0 = rl1;
                if (i + 2 < NK) { int k0 = (kb + i + 2) << 4;
                                  ra1 = __ldcg(&Arow[k0]);
                                  rm1 = __ldcg(&Wmc[k0 * 64]);
                                  rl1 = __ldcg(&Wlc[k0 * 64]); }
                __syncthreads();
#pragma unroll
                for (int kk = 0; kk < 16; kk++) {
                    float a = As[s][ty][kk];
                    am = fmaf(a, Wm[s][kk][tx], am);
                    av = fmaf(a, Wl[s][kk][tx], av);
                }
            }
            if (kh == 1) { Cm[tid] = am; Cv[tid] = av; }
            __syncthreads();
            if (kh == 0) {
                am += Cm[tid] + b_mu[col];
                av += Cv[tid] + b_lv[col];
                out[OFF_MU + row * 64 + col] = am;
                out[OFF_LV + row * 64 + col] = av;
                g_z[row * 64 + col] = am + eps[row * 64 + col] * expf(0.5f * av);
            }
            __syncthreads();
        }
    }
    grid_sync();
    // P3: dec1 [128,64]@[64,512] selu
    gemm_phase<2>(g_z, d_w1, d_b1, g_dh1, 512, 64, sm);
    grid_sync();
    // P4: dec2 [128,512]@[512,512] selu
    gemm_phase<2>(g_dh1, d_w2, d_b2, g_dh2, 512, 512, sm);
    grid_sync();
    // P5: heads + bezier + render, one CTA per batch element
    {
        int b = blockIdx.x;
        float* h   = sm;        // 512
        float* pts = sm + 512;  // 40
        float* wa  = sm + 552;  // 4
        float* cux = sm + 556;  // 192 (8B-aligned)
        float* cuy = sm + 748;  // 192 (8B-aligned)
        h[t] = __ldcg(&g_dh2[b * HIDDEN + t]);
        __syncthreads();
        // heads: warp per output, shfl reduce; literal strides per head type
        {
            int wid = t >> 5, lane = t & 31;
            for (int o = wid; o < 40; o += 16) {
                float acc = 0.f;
#pragma unroll
                for (int k = lane; k < HIDDEN; k += 32)
                    acc = fmaf(h[k], __ldg(&p_w[k * 40 + o]), acc);
#pragma unroll
                for (int off = 16; off; off >>= 1)
                    acc += __shfl_down_sync(0xffffffffu, acc, off);
                if (lane == 0) pts[o] = tanhf(acc + p_b[o]) * 12.f + 14.f;
            }
            if (wid >= 8 && wid < 10) {          // widths
                int j = wid - 8;
                float acc = 0.f;
#pragma unroll
                for (int k = lane; k < HIDDEN; k += 32)
                    acc = fmaf(h[k], __ldg(&wd_w[k * 2 + j]), acc);
#pragma unroll
                for (int off = 16; off; off >>= 1)
                    acc += __shfl_down_sync(0xffffffffu, acc, off);
                if (lane == 0) wa[j] = 2.f / (1.f + __expf(-(acc + wd_b[j]))) + 1.f;
            }
            if (wid >= 10 && wid < 12) {         // alphas
                int j = wid - 10;
                float acc = 0.f;
#pragma unroll
                for (int k = lane; k < HIDDEN; k += 32)
                    acc = fmaf(h[k], __ldg(&a_w[k * 2 + j]), acc);
#pragma unroll
                for (int off = 16; off; off >>= 1)
                    acc += __shfl_down_sync(0xffffffffu, acc, off);
                if (lane == 0) wa[2 + j] = 1.f / (1.f + __expf(-(acc + a_b[j])));
            }
        }
        __syncthreads();
        // cp out: [P,S,4,2] overlapping segments
        if (t < 48) {
            int p = t / 24, rem = t % 24;
            int s = rem / 8, kc = rem % 8;
            int k = kc / 2, c = kc & 1;
            out[OFF_CP + b * 48 + t] = pts[p * 20 + (3 * s + k) * 2 + c];
        }
        if (t < 2)            out[OFF_W + b * 2 + t] = wa[t];
        if (t >= 2 && t < 4)  out[OFF_A + b * 2 + (t - 2)] = wa[t];
        // curve samples into smem
        if (t < NPATH * MPTS * 2) {
            int i = t;
            int p = i / (MPTS * 2);
            int m = (i >> 1) % MPTS;
            int c = i & 1;
            int s = m / TSAMP, tt = m % TSAMP;
            float tv = ((float)tt + 0.5f) / (float)TSAMP;
            float u = 1.f - tv;
            float b0 = u * u * u;
            float b1 = 3.f * tv * u * u;
            float b2 = 3.f * tv * tv * u;
            float b3 = tv * tv * tv;
            const float* Pp = &pts[p * 20 + (3 * s) * 2 + c];
            float v = b0 * Pp[0] + b1 * Pp[2] + b2 * Pp[4] + b3 * Pp[6];
            (c ? cuy : cux)[p * MPTS + m] = v;
        }
        __syncthreads();
        // rasterizer: packed f32x2, 2 curve points per iteration, 4 subsamples
        for (int pix = t; pix < 784; pix += NTHR) {
            int py = pix / 28, px = pix % 28;
            float x0 = (float)px + 0.25f, x1 = (float)px + 0.75f;
            float y0 = (float)py + 0.25f, y1 = (float)py + 0.75f;
            float nx0 = -x0, nx1 = -x1, ny0 = -y0, ny1 = -y1;
            unsigned long long nx0p, nx1p, ny0p, ny1p;
            PACK2(nx0p, __float_as_uint(nx0), __float_as_uint(nx0));
            PACK2(nx1p, __float_as_uint(nx1), __float_as_uint(nx1));
            PACK2(ny0p, __float_as_uint(ny0), __float_as_uint(ny0));
            PACK2(ny1p, __float_as_uint(ny1), __float_as_uint(ny1));
            float v00 = 1.f, v01 = 1.f, v10 = 1.f, v11 = 1.f;
#pragma unroll
            for (int p = 0; p < NPATH; p++) {
                const unsigned long long* cx2 =
                    (const unsigned long long*)(cux + p * MPTS);
                const unsigned long long* cy2 =
                    (const unsigned long long*)(cuy + p * MPTS);
                float m00 = 1e30f, m01 = 1e30f, m10 = 1e30f, m11 = 1e30f;
#pragma unroll 8
                for (int i = 0; i < MPTS / 2; i++) {
                    unsigned long long cxp = cx2[i];
                    unsigned long long cyp = cy2[i];
                    unsigned long long dx0, dx1, dy0, dy1, sy0, sy1;
                    unsigned long long s00, s01, s10, s11;
                    F32X2_ADD(dx0, cxp, nx0p);
                    F32X2_ADD(dx1, cxp, nx1p);
                    F32X2_ADD(dy0, cyp, ny0p);
                    F32X2_ADD(dy1, cyp, ny1p);
                    F32X2_MUL(sy0, dy0, dy0);
                    F32X2_MUL(sy1, dy1, dy1);
                    F32X2_FMA(s00, dx0, dx0, sy0);
                    F32X2_FMA(s01, dx1, dx1, sy0);
                    F32X2_FMA(s10, dx0, dx0, sy1);
                    F32X2_FMA(s11, dx1, dx1, sy1);
                    unsigned lo, hi;
                    UNPACK2(lo, hi, s00);
                    m00 = fminf(m00, __uint_as_float(lo));
                    m00 = fminf(m00, __uint_as_float(hi));
                    UNPACK2(lo, hi, s01);
                    m01 = fminf(m01, __uint_as_float(lo));
                    m01 = fminf(m01, __uint_as_float(hi));
                    UNPACK2(lo, hi, s10);
                    m10 = fminf(m10, __uint_as_float(lo));
                    m10 = fminf(m10, __uint_as_float(hi));
                    UNPACK2(lo, hi, s11);
                    m11 = fminf(m11, __uint_as_float(lo));
                    m11 = fminf(m11, __uint_as_float(hi));
                }
                float w = wa[p] * 0.5f;
                float al = wa[2 + p];
                float d00 = sqrtf(m00 + 1e-12f);
                float d01 = sqrtf(m01 + 1e-12f);
                float d10 = sqrtf(m10 + 1e-12f);
                float d11 = sqrtf(m11 + 1e-12f);
                v00 *= 1.f - al / (1.f + __expf((d00 - w) * 2.f));
                v01 *= 1.f - al / (1.f + __expf((d01 - w) * 2.f));
                v10 *= 1.f - al / (1.f + __expf((d10 - w) * 2.f));
                v11 *= 1.f - al / (1.f + __expf((d11 - w) * 2.f));
            }
            out[OFF_REND + b * 784 + pix] = 1.f - 0.25f * (v00 + v01 + v10 + v11);
        }
    }
}

extern "C" void kernel_launch(void* const* d_in, const int* in_sizes, int n_in,
                              void* d_out, int out_size) {
    const float* x    = (const float*)d_in[0];
    const float* eps  = (const float*)d_in[1];
    const float* e_w1 = (const float*)d_in[2];
    const float* e_b1 = (const float*)d_in[3];
    const float* e_w2 = (const float*)d_in[4];
    const float* e_b2 = (const float*)d_in[5];
    const float* w_mu = (const float*)d_in[6];
    const float* b_mu = (const float*)d_in[7];
    const float* w_lv = (const float*)d_in[8];
    const float* b_lv = (const float*)d_in[9];
    const float* d_w1 = (const float*)d_in[10];
    const float* d_b1 = (const float*)d_in[11];
    const float* d_w2 = (const float*)d_in[12];
    const float* d_b2 = (const float*)d_in[13];
    const float* p_w  = (const float*)d_in[14];
    const float* p_b  = (const float*)d_in[15];
    const float* wd_w = (const float*)d_in[16];
    const float* wd_b = (const float*)d_in[17];
    const float* a_w  = (const float*)d_in[18];
    const float* a_b  = (const float*)d_in[19];
    float* out = (float*)d_out;

    mega_kernel<<<NBLK, NTHR>>>(x, eps, e_w1, e_b1, e_w2, e_b2, w_mu, b_mu,
                                w_lv, b_lv, d_w1, d_b1, d_w2, d_b2,
                                p_w, p_b, wd_w, wd_b, a_w, a_b, out);
}

// round 9
// speedup vs baseline: 1.9472x; 1.0728x over previous
#include <cuda_runtime.h>
#include <math.h>

#define BB 128
#define NBLK 128
#define NTHR 512
#define LATENT 64
#define HIDDEN 512
#define NPATH 2
#define SEG 3
#define TSAMP 32
#define MPTS (SEG*TSAMP) // 96

// output offsets (floats), concat in return order
#define OFF_REND 0
#define OFF_MU   (BB*784)
#define OFF_LV   (OFF_MU + BB*64)
#define OFF_CP   (OFF_LV + BB*64)
#define OFF_W    (OFF_CP + BB*48)
#define OFF_A    (OFF_W + BB*2)

// packed fp32x2 (Blackwell)
#define F32X2_ADD(o,a,b)   asm("add.rn.f32x2 %0,%1,%2;" : "=l"(o) : "l"(a), "l"(b))
#define F32X2_MUL(o,a,b)   asm("mul.rn.f32x2 %0,%1,%2;" : "=l"(o) : "l"(a), "l"(b))
#define F32X2_FMA(o,a,b,c) asm("fma.rn.f32x2 %0,%1,%2,%3;" : "=l"(o) : "l"(a), "l"(b), "l"(c))
#define PACK2(o,lo,hi)     asm("mov.b64 %0,{%1,%2};" : "=l"(o) : "r"(lo), "r"(hi))
#define UNPACK2(lo,hi,i)   asm("mov.b64 {%0,%1},%2;" : "=r"(lo), "=r"(hi) : "l"(i))

typedef unsigned long long u64;

// scratch (inter-phase activations)
__device__ float g_h1[BB*256];
__device__ float g_h2[BB*256];
__device__ float g_z[BB*LATENT];
__device__ float g_dh1[BB*HIDDEN];
__device__ float g_dh2[BB*HIDDEN];
__device__ unsigned g_cnt;   // zero-init; last arriver resets each barrier
__device__ unsigned g_gen;   // monotonically increasing

__device__ __forceinline__ void grid_sync() {
    __syncthreads();
    if (threadIdx.x == 0) {
        __threadfence();
        volatile unsigned* vgen = &g_gen;
        unsigned gen = *vgen;  // read BEFORE arrival
        if (atomicAdd(&g_cnt, 1u) == NBLK - 1) {
            g_cnt = 0;
            __threadfence();
            atomicAdd(&g_gen, 1u);
        } else {
            while (*vgen == gen) { __nanosleep(32); }
        }
    }
    __syncthreads();
}

// ---- pipelined tiled GEMM phase, 512 threads, K split across two halves.
// Per-half double-buffered smem (buffer = kh*2 + stage), W staged TRANSPOSED
// (row stride 18 -> conflict-free stores, contiguous per-thread reads),
// packed f32x2 inner loop (8 FFMA2), 2-ahead register prefetch, 1 bar/k-iter.
// M = BB, dims multiples of 16. ACT: 0 none, 1 leaky, 2 selu
template<int ACT>
__device__ void gemm_phase(const float* __restrict__ A, const float* __restrict__ W,
                           const float* __restrict__ bias, float* __restrict__ C,
                           int N, int K, float* sm) {
    float (*As)[16][16] = (float(*)[16][16])sm;           // [4][16][16] = 1024
    float (*Wt)[16][18] = (float(*)[16][18])(sm + 1024);  // [4][16][18] = 1152
    float* Cpart = sm + 2176;                             // 256
    int t = threadIdx.x;
    int kh = t >> 8, tid = t & 255;
    int tx = tid & 15, ty = tid >> 4;
    int Kt = K >> 4;
    int Kt0 = (Kt + 1) >> 1;        // common loop trip count
    int kbeg = kh ? Kt0 : 0;
    int nk = kh ? (Kt - Kt0) : Kt0; // this half's valid k-tiles
    int tpr = N >> 4;
    int tiles = (BB >> 4) * tpr;
    for (int tile = blockIdx.x; tile < tiles; tile += NBLK) {
        int mb = tile / tpr, nb = tile - mb * tpr;
        int row = mb * 16 + ty, col = nb * 16 + tx;
        const float* Arow = A + row * K + tx;
        const float* Wcol = W + ty * N + col;
        float ra0 = 0.f, rw0 = 0.f, ra1 = 0.f, rw1 = 0.f;
        if (0 < nk) { int k0 = kbeg << 4;
                      ra0 = __ldcg(&Arow[k0]); rw0 = __ldcg(&Wcol[(long)k0 * N]); }
        if (1 < nk) { int k0 = (kbeg + 1) << 4;
                      ra1 = __ldcg(&Arow[k0]); rw1 = __ldcg(&Wcol[(long)k0 * N]); }
        u64 acc2 = 0ull;
        for (int i = 0; i < Kt0; i++) {
            int s = (kh << 1) | (i & 1);
            bool ok = i < nk;
            if (ok) { As[s][ty][tx] = ra0; Wt[s][tx][ty] = rw0; }
            ra0 = ra1; rw0 = rw1;
            if (i + 2 < nk) { int k0 = (kbeg + i + 2) << 4;
                              ra1 = __ldcg(&Arow[k0]); rw1 = __ldcg(&Wcol[(long)k0 * N]); }
            __syncthreads();
            if (ok) {
                const u64* a2 = (const u64*)As[s][ty];  // 64B-aligned base
                const u64* w2 = (const u64*)Wt[s][tx];  // 72B-stride, 8B-aligned
#pragma unroll
                for (int j = 0; j < 8; j++)
                    F32X2_FMA(acc2, a2[j], w2[j], acc2);
            }
        }
        unsigned alo, ahi;
        UNPACK2(alo, ahi, acc2);
        float acc = __uint_as_float(alo) + __uint_as_float(ahi);
        if (kh == 1) Cpart[tid] = acc;
        __syncthreads();   // Cpart visible + all compute done
        if (kh == 0) {
            acc += Cpart[tid] + bias[col];
            if (ACT == 1) {
                acc = (acc >= 0.f) ? acc : 0.2f * acc;
            } else if (ACT == 2) {
                const float sc = 1.0507009873554805f, al = 1.6732632423543772f;
                acc = (acc > 0.f) ? sc * acc : sc * al * expm1f(acc);
            }
            C[row * N + col] = acc;
        }
        __syncthreads();   // protect smem reuse by next tile
    }
}

__global__ void __launch_bounds__(NTHR, 1)
mega_kernel(const float* __restrict__ x,    const float* __restrict__ eps,
            const float* __restrict__ e_w1, const float* __restrict__ e_b1,
            const float* __restrict__ e_w2, const float* __restrict__ e_b2,
            const float* __restrict__ w_mu, const float* __restrict__ b_mu,
            const float* __restrict__ w_lv, const float* __restrict__ b_lv,
            const float* __restrict__ d_w1, const float* __restrict__ d_b1,
            const float* __restrict__ d_w2, const float* __restrict__ d_b2,
            const float* __restrict__ p_w,  const float* __restrict__ p_b,
            const float* __restrict__ wd_w, const float* __restrict__ wd_b,
            const float* __restrict__ a_w,  const float* __restrict__ a_b,
            float* __restrict__ out) {
    __shared__ __align__(16) float sm[3840];
    int t = threadIdx.x;

    // P0: enc1 [128,784]@[784,256] leaky
    gemm_phase<1>(x, e_w1, e_b1, g_h1, 256, 784, sm);
    grid_sync();
    // P1: enc2 [128,256]@[256,256] leaky
    gemm_phase<1>(g_h1, e_w2, e_b2, g_h2, 256, 256, sm);
    grid_sync();
    // P2: mu + logvar + z fused, pipelined, transposed+packed like gemm_phase
    {
        float (*As)[16][16] = (float(*)[16][16])sm;            // [4][16][16] 1024
        float (*Wmt)[16][18] = (float(*)[16][18])(sm + 1024);  // [4][16][18] 1152
        float (*Wlt)[16][18] = (float(*)[16][18])(sm + 2176);  // [4][16][18] 1152
        float* Cm = sm + 3328;  // 256
        float* Cv = sm + 3584;  // 256
        int kh = t >> 8, tid = t & 255;
        int tx = tid & 15, ty = tid >> 4;
        const int NK = 8;       // 16 k-tiles, 8 per half
        for (int tile = blockIdx.x; tile < 32; tile += NBLK) {
            int mb = tile >> 2, nb = tile & 3;
            int row = mb * 16 + ty, col = nb * 16 + tx;
            const float* Arow = g_h2 + row * 256 + tx;
            const float* Wmc = w_mu + ty * 64 + col;
            const float* Wlc = w_lv + ty * 64 + col;
            int kb = kh * NK;
            float ra0, rm0, rl0, ra1, rm1, rl1;
            { int k0 = kb << 4;
              ra0 = __ldcg(&Arow[k0]); rm0 = __ldcg(&Wmc[k0 * 64]); rl0 = __ldcg(&Wlc[k0 * 64]); }
            { int k0 = (kb + 1) << 4;
              ra1 = __ldcg(&Arow[k0]); rm1 = __ldcg(&Wmc[k0 * 64]); rl1 = __ldcg(&Wlc[k0 * 64]); }
            u64 am2 = 0ull, av2 = 0ull;
            for (int i = 0; i < NK; i++) {
                int s = (kh << 1) | (i & 1);
                As[s][ty][tx] = ra0; Wmt[s][tx][ty] = rm0; Wlt[s][tx][ty] = rl0;
                ra0 = ra1; rm0 = rm1; rl0 = rl1;
                if (i + 2 < NK) { int k0 = (kb + i + 2) << 4;
                                  ra1 = __ldcg(&Arow[k0]);
                                  rm1 = __ldcg(&Wmc[k0 * 64]);
                                  rl1 = __ldcg(&Wlc[k0 * 64]); }
                __syncthreads();
                const u64* a2 = (const u64*)As[s][ty];
                const u64* m2 = (const u64*)Wmt[s][tx];
                const u64* l2 = (const u64*)Wlt[s][tx];
#pragma unroll
                for (int j = 0; j < 8; j++) {
                    u64 av_ = a2[j];
                    F32X2_FMA(am2, av_, m2[j], am2);
                    F32X2_FMA(av2, av_, l2[j], av2);
                }
            }
            unsigned lo, hi;
            UNPACK2(lo, hi, am2);
            float am = __uint_as_float(lo) + __uint_as_float(hi);
            UNPACK2(lo, hi, av2);
            float av = __uint_as_float(lo) + __uint_as_float(hi);
            if (kh == 1) { Cm[tid] = am; Cv[tid] = av; }
            __syncthreads();
            if (kh == 0) {
                am += Cm[tid] + b_mu[col];
                av += Cv[tid] + b_lv[col];
                out[OFF_MU + row * 64 + col] = am;
                out[OFF_LV + row * 64 + col] = av;
                g_z[row * 64 + col] = am + eps[row * 64 + col] * expf(0.5f * av);
            }
            __syncthreads();
        }
    }
    grid_sync();
    // P3: dec1 [128,64]@[64,512] selu
    gemm_phase<2>(g_z, d_w1, d_b1, g_dh1, 512, 64, sm);
    grid_sync();
    // P4: dec2 [128,512]@[512,512] selu
    gemm_phase<2>(g_dh1, d_w2, d_b2, g_dh2, 512, 512, sm);
    grid_sync();
    // P5: heads + bezier + render, one CTA per batch element
    {
        int b = blockIdx.x;
        float* h   = sm;        // 512
        float* pts = sm + 512;  // 40
        float* wa  = sm + 552;  // 4
        float* cux = sm + 556;  // 192 (8B-aligned)
        float* cuy = sm + 748;  // 192 (8B-aligned)
        h[t] = __ldcg(&g_dh2[b * HIDDEN + t]);
        __syncthreads();
        // heads: warp per output, shfl reduce; literal strides per head type
        {
            int wid = t >> 5, lane = t & 31;
            for (int o = wid; o < 40; o += 16) {
                float acc = 0.f;
#pragma unroll
                for (int k = lane; k < HIDDEN; k += 32)
                    acc = fmaf(h[k], __ldg(&p_w[k * 40 + o]), acc);
#pragma unroll
                for (int off = 16; off; off >>= 1)
                    acc += __shfl_down_sync(0xffffffffu, acc, off);
                if (lane == 0) pts[o] = tanhf(acc + p_b[o]) * 12.f + 14.f;
            }
            if (wid >= 8 && wid < 10) {          // widths
                int j = wid - 8;
                float acc = 0.f;
#pragma unroll
                for (int k = lane; k < HIDDEN; k += 32)
                    acc = fmaf(h[k], __ldg(&wd_w[k * 2 + j]), acc);
#pragma unroll
                for (int off = 16; off; off >>= 1)
                    acc += __shfl_down_sync(0xffffffffu, acc, off);
                if (lane == 0) wa[j] = 2.f / (1.f + __expf(-(acc + wd_b[j]))) + 1.f;
            }
            if (wid >= 10 && wid < 12) {         // alphas
                int j = wid - 10;
                float acc = 0.f;
#pragma unroll
                for (int k = lane; k < HIDDEN; k += 32)
                    acc = fmaf(h[k], __ldg(&a_w[k * 2 + j]), acc);
#pragma unroll
                for (int off = 16; off; off >>= 1)
                    acc += __shfl_down_sync(0xffffffffu, acc, off);
                if (lane == 0) wa[2 + j] = 1.f / (1.f + __expf(-(acc + a_b[j])));
            }
        }
        __syncthreads();
        // cp out: [P,S,4,2] overlapping segments
        if (t < 48) {
            int p = t / 24, rem = t % 24;
            int s = rem / 8, kc = rem % 8;
            int k = kc / 2, c = kc & 1;
            out[OFF_CP + b * 48 + t] = pts[p * 20 + (3 * s + k) * 2 + c];
        }
        if (t < 2)            out[OFF_W + b * 2 + t] = wa[t];
        if (t >= 2 && t < 4)  out[OFF_A + b * 2 + (t - 2)] = wa[t];
        // curve samples into smem
        if (t < NPATH * MPTS * 2) {
            int i = t;
            int p = i / (MPTS * 2);
            int m = (i >> 1) % MPTS;
            int c = i & 1;
            int s = m / TSAMP, tt = m % TSAMP;
            float tv = ((float)tt + 0.5f) / (float)TSAMP;
            float u = 1.f - tv;
            float b0 = u * u * u;
            float b1 = 3.f * tv * u * u;
            float b2 = 3.f * tv * tv * u;
            float b3 = tv * tv * tv;
            const float* Pp = &pts[p * 20 + (3 * s) * 2 + c];
            float v = b0 * Pp[0] + b1 * Pp[2] + b2 * Pp[4] + b3 * Pp[6];
            (c ? cuy : cux)[p * MPTS + m] = v;
        }
        __syncthreads();
        // rasterizer: packed f32x2, 2 curve points per iteration, 4 subsamples
        for (int pix = t; pix < 784; pix += NTHR) {
            int py = pix / 28, px = pix % 28;
            float x0 = (float)px + 0.25f, x1 = (float)px + 0.75f;
            float y0 = (float)py + 0.25f, y1 = (float)py + 0.75f;
            float nx0 = -x0, nx1 = -x1, ny0 = -y0, ny1 = -y1;
            u64 nx0p, nx1p, ny0p, ny1p;
            PACK2(nx0p, __float_as_uint(nx0), __float_as_uint(nx0));
            PACK2(nx1p, __float_as_uint(nx1), __float_as_uint(nx1));
            PACK2(ny0p, __float_as_uint(ny0), __float_as_uint(ny0));
            PACK2(ny1p, __float_as_uint(ny1), __float_as_uint(ny1));
            float v00 = 1.f, v01 = 1.f, v10 = 1.f, v11 = 1.f;
#pragma unroll
            for (int p = 0; p < NPATH; p++) {
                const u64* cx2 = (const u64*)(cux + p * MPTS);
                const u64* cy2 = (const u64*)(cuy + p * MPTS);
                float m00 = 1e30f, m01 = 1e30f, m10 = 1e30f, m11 = 1e30f;
#pragma unroll 8
                for (int i = 0; i < MPTS / 2; i++) {
                    u64 cxp = cx2[i];
                    u64 cyp = cy2[i];
                    u64 dx0, dx1, dy0, dy1, sy0, sy1;
                    u64 s00, s01, s10, s11;
                    F32X2_ADD(dx0, cxp, nx0p);
                    F32X2_ADD(dx1, cxp, nx1p);
                    F32X2_ADD(dy0, cyp, ny0p);
                    F32X2_ADD(dy1, cyp, ny1p);
                    F32X2_MUL(sy0, dy0, dy0);
                    F32X2_MUL(sy1, dy1, dy1);
                    F32X2_FMA(s00, dx0, dx0, sy0);
                    F32X2_FMA(s01, dx1, dx1, sy0);
                    F32X2_FMA(s10, dx0, dx0, sy1);
                    F32X2_FMA(s11, dx1, dx1, sy1);
                    unsigned lo, hi;
                    UNPACK2(lo, hi, s00);
                    m00 = fminf(m00, __uint_as_float(lo));
                    m00 = fminf(m00, __uint_as_float(hi));
                    UNPACK2(lo, hi, s01);
                    m01 = fminf(m01, __uint_as_float(lo));
                    m01 = fminf(m01, __uint_as_float(hi));
                    UNPACK2(lo, hi, s10);
                    m10 = fminf(m10, __uint_as_float(lo));
                    m10 = fminf(m10, __uint_as_float(hi));
                    UNPACK2(lo, hi, s11);
                    m11 = fminf(m11, __uint_as_float(lo));
                    m11 = fminf(m11, __uint_as_float(hi));
                }
                float w = wa[p] * 0.5f;
                float al = wa[2 + p];
                float d00 = sqrtf(m00 + 1e-12f);
                float d01 = sqrtf(m01 + 1e-12f);
                float d10 = sqrtf(m10 + 1e-12f);
                float d11 = sqrtf(m11 + 1e-12f);
                v00 *= 1.f - al / (1.f + __expf((d00 - w) * 2.f));
                v01 *= 1.f - al / (1.f + __expf((d01 - w) * 2.f));
                v10 *= 1.f - al / (1.f + __expf((d10 - w) * 2.f));
                v11 *= 1.f - al / (1.f + __expf((d11 - w) * 2.f));
            }
            out[OFF_REND + b * 784 + pix] = 1.f - 0.25f * (v00 + v01 + v10 + v11);
        }
    }
}

extern "C" void kernel_launch(void* const* d_in, const int* in_sizes, int n_in,
                              void* d_out, int out_size) {
    const float* x    = (const float*)d_in[0];
    const float* eps  = (const float*)d_in[1];
    const float* e_w1 = (const float*)d_in[2];
    const float* e_b1 = (const float*)d_in[3];
    const float* e_w2 = (const float*)d_in[4];
    const float* e_b2 = (const float*)d_in[5];
    const float* w_mu = (const float*)d_in[6];
    const float* b_mu = (const float*)d_in[7];
    const float* w_lv = (const float*)d_in[8];
    const float* b_lv = (const float*)d_in[9];
    const float* d_w1 = (const float*)d_in[10];
    const float* d_b1 = (const float*)d_in[11];
    const float* d_w2 = (const float*)d_in[12];
    const float* d_b2 = (const float*)d_in[13];
    const float* p_w  = (const float*)d_in[14];
    const float* p_b  = (const float*)d_in[15];
    const float* wd_w = (const float*)d_in[16];
    const float* wd_b = (const float*)d_in[17];
    const float* a_w  = (const float*)d_in[18];
    const float* a_b  = (const float*)d_in[19];
    float* out = (float*)d_out;

    mega_kernel<<<NBLK, NTHR>>>(x, eps, e_w1, e_b1, e_w2, e_b2, w_mu, b_mu,
                                w_lv, b_lv, d_w1, d_b1, d_w2, d_b2,
                                p_w, p_b, wd_w, wd_b, a_w, a_b, out);
}

// round 12
// speedup vs baseline: 2.0911x; 1.0739x over previous
#include <cuda_runtime.h>
#include <math.h>

#define BB 128
#define NBLK 128
#define NTHR 512
#define LATENT 64
#define HIDDEN 512
#define NPATH 2
#define SEG 3
#define TSAMP 32
#define MPTS (SEG*TSAMP) // 96

// output offsets (floats), concat in return order
#define OFF_REND 0
#define OFF_MU   (BB*784)
#define OFF_LV   (OFF_MU + BB*64)
#define OFF_CP   (OFF_LV + BB*64)
#define OFF_W    (OFF_CP + BB*48)
#define OFF_A    (OFF_W + BB*2)

// packed fp32x2 (Blackwell)
#define F32X2_ADD(o,a,b)   asm("add.rn.f32x2 %0,%1,%2;" : "=l"(o) : "l"(a), "l"(b))
#define F32X2_MUL(o,a,b)   asm("mul.rn.f32x2 %0,%1,%2;" : "=l"(o) : "l"(a), "l"(b))
#define F32X2_FMA(o,a,b,c) asm("fma.rn.f32x2 %0,%1,%2,%3;" : "=l"(o) : "l"(a), "l"(b), "l"(c))
#define PACK2(o,lo,hi)     asm("mov.b64 %0,{%1,%2};" : "=l"(o) : "r"(lo), "r"(hi))
#define UNPACK2(lo,hi,i)   asm("mov.b64 {%0,%1},%2;" : "=r"(lo), "=r"(hi) : "l"(i))

typedef unsigned long long u64;

// scratch (inter-phase activations)
__device__ float g_h1[BB*256];
__device__ float g_h2[BB*256];
__device__ float g_z[BB*LATENT];
__device__ float g_dh1[BB*HIDDEN];
__device__ float g_dh2[BB*HIDDEN];
__device__ unsigned g_cnt;   // zero-init; last arriver resets each barrier
__device__ unsigned g_gen;   // monotonically increasing

__device__ __forceinline__ void grid_sync() {
    __syncthreads();
    if (threadIdx.x == 0) {
        __threadfence();
        volatile unsigned* vgen = &g_gen;
        unsigned gen = *vgen;  // read BEFORE arrival
        if (atomicAdd(&g_cnt, 1u) == NBLK - 1) {
            g_cnt = 0;
            __threadfence();
            atomicAdd(&g_gen, 1u);
        } else {
            while (*vgen == gen) { __nanosleep(32); }
        }
    }
    __syncthreads();
}

// ---- pipelined tiled GEMM phase, 512 threads, K split across two halves.
// Per-half double-buffered smem, W staged transposed (stride 18), packed
// f32x2 inner loop, 2-ahead register prefetch, 1 bar per k-iter. (P0/P1)
template<int ACT>
__device__ void gemm_phase(const float* __restrict__ A, const float* __restrict__ W,
                           const float* __restrict__ bias, float* __restrict__ C,
                           int N, int K, float* sm) {
    float (*As)[16][16] = (float(*)[16][16])sm;           // [4][16][16] = 1024
    float (*Wt)[16][18] = (float(*)[16][18])(sm + 1024);  // [4][16][18] = 1152
    float* Cpart = sm + 2176;                             // 256
    int t = threadIdx.x;
    int kh = t >> 8, tid = t & 255;
    int tx = tid & 15, ty = tid >> 4;
    int Kt = K >> 4;
    int Kt0 = (Kt + 1) >> 1;        // common loop trip count
    int kbeg = kh ? Kt0 : 0;
    int nk = kh ? (Kt - Kt0) : Kt0; // this half's valid k-tiles
    int tpr = N >> 4;
    int tiles = (BB >> 4) * tpr;
    for (int tile = blockIdx.x; tile < tiles; tile += NBLK) {
        int mb = tile / tpr, nb = tile - mb * tpr;
        int row = mb * 16 + ty, col = nb * 16 + tx;
        const float* Arow = A + row * K + tx;
        const float* Wcol = W + ty * N + col;
        float ra0 = 0.f, rw0 = 0.f, ra1 = 0.f, rw1 = 0.f;
        if (0 < nk) { int k0 = kbeg << 4;
                      ra0 = __ldcg(&Arow[k0]); rw0 = __ldcg(&Wcol[(long)k0 * N]); }
        if (1 < nk) { int k0 = (kbeg + 1) << 4;
                      ra1 = __ldcg(&Arow[k0]); rw1 = __ldcg(&Wcol[(long)k0 * N]); }
        u64 acc2 = 0ull;
        for (int i = 0; i < Kt0; i++) {
            int s = (kh << 1) | (i & 1);
            bool ok = i < nk;
            if (ok) { As[s][ty][tx] = ra0; Wt[s][tx][ty] = rw0; }
            ra0 = ra1; rw0 = rw1;
            if (i + 2 < nk) { int k0 = (kbeg + i + 2) << 4;
                              ra1 = __ldcg(&Arow[k0]); rw1 = __ldcg(&Wcol[(long)k0 * N]); }
            __syncthreads();
            if (ok) {
                const u64* a2 = (const u64*)As[s][ty];
                const u64* w2 = (const u64*)Wt[s][tx];
#pragma unroll
                for (int j = 0; j < 8; j++)
                    F32X2_FMA(acc2, a2[j], w2[j], acc2);
            }
        }
        unsigned alo, ahi;
        UNPACK2(alo, ahi, acc2);
        float acc = __uint_as_float(alo) + __uint_as_float(ahi);
        if (kh == 1) Cpart[tid] = acc;
        __syncthreads();
        if (kh == 0) {
            acc += Cpart[tid] + bias[col];
            if (ACT == 1) {
                acc = (acc >= 0.f) ? acc : 0.2f * acc;
            } else if (ACT == 2) {
                const float sc = 1.0507009873554805f, al = 1.6732632423543772f;
                acc = (acc > 0.f) ? sc * acc : sc * al * expm1f(acc);
            }
            C[row * N + col] = acc;
        }
        __syncthreads();
    }
}

// ---- single-tile 16x32 GEMM phase, 512 threads, one output per thread.
// Requires (BB/16)*(N/32) == NBLK tiles exactly and K % 32 == 0.
// K=32 per iter, double-buffered, W transposed (stride 34), 16 FFMA2 inner.
template<int ACT>
__device__ void gemm32_phase(const float* __restrict__ A, const float* __restrict__ W,
                             const float* __restrict__ bias, float* __restrict__ C,
                             int N, int K, float* sm) {
    float (*As)[16][32] = (float(*)[16][32])sm;           // [2][16][32] = 1024
    float (*Wt)[32][34] = (float(*)[32][34])(sm + 1024);  // [2][32][34] = 2176
    int t = threadIdx.x;
    int tx = t & 31, ty = t >> 5;    // ty 0..15
    int tpr = N >> 5;
    int tile = blockIdx.x;
    int mb = tile / tpr, nb = tile - mb * tpr;
    int row = mb * 16 + ty, col = nb * 32 + tx;
    const float* Arow = A + row * K + tx;
    const float* W0 = W + col;
    int KT = K >> 5;
    float ra0 = 0.f, rwa0 = 0.f, rwb0 = 0.f, ra1 = 0.f, rwa1 = 0.f, rwb1 = 0.f;
    {   // stage 0 prologue (KT >= 1 always)
        ra0  = __ldcg(&Arow[0]);
        rwa0 = __ldcg(&W0[(long)ty * N]);
        rwb0 = __ldcg(&W0[(long)(16 + ty) * N]);
    }
    if (KT > 1) {
        ra1  = __ldcg(&Arow[32]);
        rwa1 = __ldcg(&W0[(long)(32 + ty) * N]);
        rwb1 = __ldcg(&W0[(long)(48 + ty) * N]);
    }
    u64 acc2 = 0ull;
    for (int i = 0; i < KT; i++) {
        int s = i & 1;
        As[s][ty][tx]      = ra0;
        Wt[s][tx][ty]      = rwa0;
        Wt[s][tx][ty + 16] = rwb0;
        ra0 = ra1; rwa0 = rwa1; rwb0 = rwb1;
        if (i + 2 < KT) {
            int k0 = (i + 2) << 5;
            ra1  = __ldcg(&Arow[k0]);
            rwa1 = __ldcg(&W0[(long)(k0 + ty) * N]);
            rwb1 = __ldcg(&W0[(long)(k0 + 16 + ty) * N]);
        }
        __syncthreads();
        const u64* a2 = (const u64*)As[s][ty];   // warp-broadcast reads
        const u64* w2 = (const u64*)Wt[s][tx];   // contiguous, 8B-aligned
#pragma unroll
        for (int j = 0; j < 16; j++)
            F32X2_FMA(acc2, a2[j], w2[j], acc2);
    }
    unsigned alo, ahi;
    UNPACK2(alo, ahi, acc2);
    float acc = __uint_as_float(alo) + __uint_as_float(ahi) + bias[col];
    if (ACT == 1) {
        acc = (acc >= 0.f) ? acc : 0.2f * acc;
    } else if (ACT == 2) {
        const float sc = 1.0507009873554805f, al = 1.6732632423543772f;
        acc = (acc > 0.f) ? sc * acc : sc * al * expm1f(acc);
    }
    C[row * N + col] = acc;
}

__global__ void __launch_bounds__(NTHR, 1)
mega_kernel(const float* __restrict__ x,    const float* __restrict__ eps,
            const float* __restrict__ e_w1, const float* __restrict__ e_b1,
            const float* __restrict__ e_w2, const float* __restrict__ e_b2,
            const float* __restrict__ w_mu, const float* __restrict__ b_mu,
            const float* __restrict__ w_lv, const float* __restrict__ b_lv,
            const float* __restrict__ d_w1, const float* __restrict__ d_b1,
            const float* __restrict__ d_w2, const float* __restrict__ d_b2,
            const float* __restrict__ p_w,  const float* __restrict__ p_b,
            const float* __restrict__ wd_w, const float* __restrict__ wd_b,
            const float* __restrict__ a_w,  const float* __restrict__ a_b,
            float* __restrict__ out) {
    __shared__ __align__(16) float sm[3840];
    int t = threadIdx.x;

    // P0: enc1 [128,784]@[784,256] leaky
    gemm_phase<1>(x, e_w1, e_b1, g_h1, 256, 784, sm);
    grid_sync();
    // P1: enc2 [128,256]@[256,256] leaky
    gemm_phase<1>(g_h1, e_w2, e_b2, g_h2, 256, 256, sm);
    grid_sync();
    // P2: mu + logvar + z fused, pipelined, transposed+packed
    {
        float (*As)[16][16] = (float(*)[16][16])sm;            // [4][16][16] 1024
        float (*Wmt)[16][18] = (float(*)[16][18])(sm + 1024);  // [4][16][18] 1152
        float (*Wlt)[16][18] = (float(*)[16][18])(sm + 2176);  // [4][16][18] 1152
        float* Cm = sm + 3328;  // 256
        float* Cv = sm + 3584;  // 256
        int kh = t >> 8, tid = t & 255;
        int tx = tid & 15, ty = tid >> 4;
        const int NK = 8;       // 16 k-tiles, 8 per half
        for (int tile = blockIdx.x; tile < 32; tile += NBLK) {
            int mb = tile >> 2, nb = tile & 3;
            int row = mb * 16 + ty, col = nb * 16 + tx;
            const float* Arow = g_h2 + row * 256 + tx;
            const float* Wmc = w_mu + ty * 64 + col;
            const float* Wlc = w_lv + ty * 64 + col;
            int kb = kh * NK;
            float ra0, rm0, rl0, ra1, rm1, rl1;
            { int k0 = kb << 4;
              ra0 = __ldcg(&Arow[k0]); rm0 = __ldcg(&Wmc[k0 * 64]); rl0 = __ldcg(&Wlc[k0 * 64]); }
            { int k0 = (kb + 1) << 4;
              ra1 = __ldcg(&Arow[k0]); rm1 = __ldcg(&Wmc[k0 * 64]); rl1 = __ldcg(&Wlc[k0 * 64]); }
            u64 am2 = 0ull, av2 = 0ull;
            for (int i = 0; i < NK; i++) {
                int s = (kh << 1) | (i & 1);
                As[s][ty][tx] = ra0; Wmt[s][tx][ty] = rm0; Wlt[s][tx][ty] = rl0;
                ra0 = ra1; rm0 = rm1; rl0 = rl1;
                if (i + 2 < NK) { int k0 = (kb + i + 2) << 4;
                                  ra1 = __ldcg(&Arow[k0]);
                                  rm1 = __ldcg(&Wmc[k0 * 64]);
                                  rl1 = __ldcg(&Wlc[k0 * 64]); }
                __syncthreads();
                const u64* a2 = (const u64*)As[s][ty];
                const u64* m2 = (const u64*)Wmt[s][tx];
                const u64* l2 = (const u64*)Wlt[s][tx];
#pragma unroll
                for (int j = 0; j < 8; j++) {
                    u64 av_ = a2[j];
                    F32X2_FMA(am2, av_, m2[j], am2);
                    F32X2_FMA(av2, av_, l2[j], av2);
                }
            }
            unsigned lo, hi;
            UNPACK2(lo, hi, am2);
            float am = __uint_as_float(lo) + __uint_as_float(hi);
            UNPACK2(lo, hi, av2);
            float av = __uint_as_float(lo) + __uint_as_float(hi);
            if (kh == 1) { Cm[tid] = am; Cv[tid] = av; }
            __syncthreads();
            if (kh == 0) {
                am += Cm[tid] + b_mu[col];
                av += Cv[tid] + b_lv[col];
                out[OFF_MU + row * 64 + col] = am;
                out[OFF_LV + row * 64 + col] = av;
                g_z[row * 64 + col] = am + eps[row * 64 + col] * expf(0.5f * av);
            }
            __syncthreads();
        }
    }
    grid_sync();
    // P3: dec1 [128,64]@[64,512] selu — single tile per CTA
    gemm32_phase<2>(g_z, d_w1, d_b1, g_dh1, 512, 64, sm);
    grid_sync();
    // P4: dec2 [128,512]@[512,512] selu — single tile per CTA
    gemm32_phase<2>(g_dh1, d_w2, d_b2, g_dh2, 512, 512, sm);
    grid_sync();
    // P5: heads + bezier + render, one CTA per batch element
    {
        int b = blockIdx.x;
        float* h   = sm;        // 512
        float* pts = sm + 512;  // 40
        float* wa  = sm + 552;  // 4
        float* cux = sm + 556;  // 192 (8B-aligned)
        float* cuy = sm + 748;  // 192 (8B-aligned)
        h[t] = __ldcg(&g_dh2[b * HIDDEN + t]);
        __syncthreads();
        // heads: warp per output, shfl reduce
        {
            int wid = t >> 5, lane = t & 31;
            for (int o = wid; o < 40; o += 16) {
                float acc = 0.f;
#pragma unroll
                for (int k = lane; k < HIDDEN; k += 32)
                    acc = fmaf(h[k], __ldg(&p_w[k * 40 + o]), acc);
#pragma unroll
                for (int off = 16; off; off >>= 1)
                    acc += __shfl_down_sync(0xffffffffu, acc, off);
                if (lane == 0) pts[o] = tanhf(acc + p_b[o]) * 12.f + 14.f;
            }
            if (wid >= 8 && wid < 10) {          // widths
                int j = wid - 8;
                float acc = 0.f;
#pragma unroll
                for (int k = lane; k < HIDDEN; k += 32)
                    acc = fmaf(h[k], __ldg(&wd_w[k * 2 + j]), acc);
#pragma unroll
                for (int off = 16; off; off >>= 1)
                    acc += __shfl_down_sync(0xffffffffu, acc, off);
                if (lane == 0) wa[j] = 2.f / (1.f + __expf(-(acc + wd_b[j]))) + 1.f;
            }
            if (wid >= 10 && wid < 12) {         // alphas
                int j = wid - 10;
                float acc = 0.f;
#pragma unroll
                for (int k = lane; k < HIDDEN; k += 32)
                    acc = fmaf(h[k], __ldg(&a_w[k * 2 + j]), acc);
#pragma unroll
                for (int off = 16; off; off >>= 1)
                    acc += __shfl_down_sync(0xffffffffu, acc, off);
                if (lane == 0) wa[2 + j] = 1.f / (1.f + __expf(-(acc + a_b[j])));
            }
        }
        __syncthreads();
        // cp out: [P,S,4,2] overlapping segments
        if (t < 48) {
            int p = t / 24, rem = t % 24;
            int s = rem / 8, kc = rem % 8;
            int k = kc / 2, c = kc & 1;
            out[OFF_CP + b * 48 + t] = pts[p * 20 + (3 * s + k) * 2 + c];
        }
        if (t < 2)            out[OFF_W + b * 2 + t] = wa[t];
        if (t >= 2 && t < 4)  out[OFF_A + b * 2 + (t - 2)] = wa[t];
        // curve samples into smem
        if (t < NPATH * MPTS * 2) {
            int i = t;
            int p = i / (MPTS * 2);
            int m = (i >> 1) % MPTS;
            int c = i & 1;
            int s = m / TSAMP, tt = m % TSAMP;
            float tv = ((float)tt + 0.5f) / (float)TSAMP;
            float u = 1.f - tv;
            float b0 = u * u * u;
            float b1 = 3.f * tv * u * u;
            float b2 = 3.f * tv * tv * u;
            float b3 = tv * tv * tv;
            const float* Pp = &pts[p * 20 + (3 * s) * 2 + c];
            float v = b0 * Pp[0] + b1 * Pp[2] + b2 * Pp[4] + b3 * Pp[6];
            (c ? cuy : cux)[p * MPTS + m] = v;
        }
        __syncthreads();
        // rasterizer: packed f32x2, 2 curve points per iteration, 4 subsamples
        for (int pix = t; pix < 784; pix += NTHR) {
            int py = pix / 28, px = pix % 28;
            float x0 = (float)px + 0.25f, x1 = (float)px + 0.75f;
            float y0 = (float)py + 0.25f, y1 = (float)py + 0.75f;
            float nx0 = -x0, nx1 = -x1, ny0 = -y0, ny1 = -y1;
            u64 nx0p, nx1p, ny0p, ny1p;
            PACK2(nx0p, __float_as_uint(nx0), __float_as_uint(nx0));
            PACK2(nx1p, __float_as_uint(nx1), __float_as_uint(nx1));
            PACK2(ny0p, __float_as_uint(ny0), __float_as_uint(ny0));
            PACK2(ny1p, __float_as_uint(ny1), __float_as_uint(ny1));
            float v00 = 1.f, v01 = 1.f, v10 = 1.f, v11 = 1.f;
#pragma unroll
            for (int p = 0; p < NPATH; p++) {
                const u64* cx2 = (const u64*)(cux + p * MPTS);
                const u64* cy2 = (const u64*)(cuy + p * MPTS);
                float m00 = 1e30f, m01 = 1e30f, m10 = 1e30f, m11 = 1e30f;
#pragma unroll 8
                for (int i = 0; i < MPTS / 2; i++) {
                    u64 cxp = cx2[i];
                    u64 cyp = cy2[i];
                    u64 dx0, dx1, dy0, dy1, sy0, sy1;
                    u64 s00, s01, s10, s11;
                    F32X2_ADD(dx0, cxp, nx0p);
                    F32X2_ADD(dx1, cxp, nx1p);
                    F32X2_ADD(dy0, cyp, ny0p);
                    F32X2_ADD(dy1, cyp, ny1p);
                    F32X2_MUL(sy0, dy0, dy0);
                    F32X2_MUL(sy1, dy1, dy1);
                    F32X2_FMA(s00, dx0, dx0, sy0);
                    F32X2_FMA(s01, dx1, dx1, sy0);
                    F32X2_FMA(s10, dx0, dx0, sy1);
                    F32X2_FMA(s11, dx1, dx1, sy1);
                    unsigned lo, hi;
                    UNPACK2(lo, hi, s00);
                    m00 = fminf(m00, __uint_as_float(lo));
                    m00 = fminf(m00, __uint_as_float(hi));
                    UNPACK2(lo, hi, s01);
                    m01 = fminf(m01, __uint_as_float(lo));
                    m01 = fminf(m01, __uint_as_float(hi));
                    UNPACK2(lo, hi, s10);
                    m10 = fminf(m10, __uint_as_float(lo));
                    m10 = fminf(m10, __uint_as_float(hi));
                    UNPACK2(lo, hi, s11);
                    m11 = fminf(m11, __uint_as_float(lo));
                    m11 = fminf(m11, __uint_as_float(hi));
                }
                float w = wa[p] * 0.5f;
                float al = wa[2 + p];
                float t00 = m00 + 1e-12f, t01 = m01 + 1e-12f;
                float t10 = m10 + 1e-12f, t11 = m11 + 1e-12f;
                float d00 = t00 * rsqrtf(t00);
                float d01 = t01 * rsqrtf(t01);
                float d10 = t10 * rsqrtf(t10);
                float d11 = t11 * rsqrtf(t11);
                v00 *= 1.f - __fdividef(al, 1.f + __expf((d00 - w) * 2.f));
                v01 *= 1.f - __fdividef(al, 1.f + __expf((d01 - w) * 2.f));
                v10 *= 1.f - __fdividef(al, 1.f + __expf((d10 - w) * 2.f));
                v11 *= 1.f - __fdividef(al, 1.f + __expf((d11 - w) * 2.f));
            }
            out[OFF_REND + b * 784 + pix] = 1.f - 0.25f * (v00 + v01 + v10 + v11);
        }
    }
}

extern "C" void kernel_launch(void* const* d_in, const int* in_sizes, int n_in,
                              void* d_out, int out_size) {
    const float* x    = (const float*)d_in[0];
    const float* eps  = (const float*)d_in[1];
    const float* e_w1 = (const float*)d_in[2];
    const float* e_b1 = (const float*)d_in[3];
    const float* e_w2 = (const float*)d_in[4];
    const float* e_b2 = (const float*)d_in[5];
    const float* w_mu = (const float*)d_in[6];
    const float* b_mu = (const float*)d_in[7];
    const float* w_lv = (const float*)d_in[8];
    const float* b_lv = (const float*)d_in[9];
    const float* d_w1 = (const float*)d_in[10];
    const float* d_b1 = (const float*)d_in[11];
    const float* d_w2 = (const float*)d_in[12];
    const float* d_b2 = (const float*)d_in[13];
    const float* p_w  = (const float*)d_in[14];
    const float* p_b  = (const float*)d_in[15];
    const float* wd_w = (const float*)d_in[16];
    const float* wd_b = (const float*)d_in[17];
    const float* a_w  = (const float*)d_in[18];
    const float* a_b  = (const float*)d_in[19];
    float* out = (float*)d_out;

    mega_kernel<<<NBLK, NTHR>>>(x, eps, e_w1, e_b1, e_w2, e_b2, w_mu, b_mu,
                                w_lv, b_lv, d_w1, d_b1, d_w2, d_b2,
                                p_w, p_b, wd_w, wd_b, a_w, a_b, out);
}

// round 13
// speedup vs baseline: 2.1015x; 1.0050x over previous
#include <cuda_runtime.h>
#include <math.h>

#define BB 128
#define NBLK 128
#define NTHR 512
#define LATENT 64
#define HIDDEN 512
#define NPATH 2
#define SEG 3
#define TSAMP 32
#define MPTS (SEG*TSAMP) // 96

// output offsets (floats), concat in return order
#define OFF_REND 0
#define OFF_MU   (BB*784)
#define OFF_LV   (OFF_MU + BB*64)
#define OFF_CP   (OFF_LV + BB*64)
#define OFF_W    (OFF_CP + BB*48)
#define OFF_A    (OFF_W + BB*2)

// packed fp32x2 (Blackwell)
#define F32X2_ADD(o,a,b)   asm("add.rn.f32x2 %0,%1,%2;" : "=l"(o) : "l"(a), "l"(b))
#define F32X2_MUL(o,a,b)   asm("mul.rn.f32x2 %0,%1,%2;" : "=l"(o) : "l"(a), "l"(b))
#define F32X2_FMA(o,a,b,c) asm("fma.rn.f32x2 %0,%1,%2,%3;" : "=l"(o) : "l"(a), "l"(b), "l"(c))
#define PACK2(o,lo,hi)     asm("mov.b64 %0,{%1,%2};" : "=l"(o) : "r"(lo), "r"(hi))
#define UNPACK2(lo,hi,i)   asm("mov.b64 {%0,%1},%2;" : "=r"(lo), "=r"(hi) : "l"(i))

typedef unsigned long long u64;

// scratch (inter-phase activations)
__device__ float g_h1[BB*256];
__device__ float g_h2[BB*256];
__device__ float g_z[BB*LATENT];
__device__ float g_dh1[BB*HIDDEN];
__device__ float g_dh2[BB*HIDDEN];
__device__ unsigned g_cnt;   // zero-init; last arriver resets each barrier
__device__ unsigned g_gen;   // monotonically increasing

__device__ __forceinline__ void grid_sync() {
    __syncthreads();
    if (threadIdx.x == 0) {
        __threadfence();
        volatile unsigned* vgen = &g_gen;
        unsigned gen = *vgen;  // read BEFORE arrival
        if (atomicAdd(&g_cnt, 1u) == NBLK - 1) {
            g_cnt = 0;
            __threadfence();
            atomicAdd(&g_gen, 1u);
        } else {
            while (*vgen == gen) { __nanosleep(32); }
        }
    }
    __syncthreads();
}

// ---- 4-stage pipelined tiled GEMM phase, 512 threads, K split 2 halves.
// Per-half 4 smem buffers (s = kh*4 + i%4) + 3-ahead register prefetch,
// W staged transposed (stride 18), packed f32x2 inner, 1 bar/k-iter.
template<int ACT>
__device__ void gemm_phase(const float* __restrict__ A, const float* __restrict__ W,
                           const float* __restrict__ bias, float* __restrict__ C,
                           int N, int K, float* sm) {
    float (*As)[16][16] = (float(*)[16][16])sm;           // [8][16][16] = 2048
    float (*Wt)[16][18] = (float(*)[16][18])(sm + 2048);  // [8][16][18] = 2304
    float* Cpart = sm + 4352;                             // 256
    int t = threadIdx.x;
    int kh = t >> 8, tid = t & 255;
    int tx = tid & 15, ty = tid >> 4;
    int Kt = K >> 4;
    int Kt0 = (Kt + 1) >> 1;
    int kbeg = kh ? Kt0 : 0;
    int nk = kh ? (Kt - Kt0) : Kt0;
    int tpr = N >> 4;
    int tiles = (BB >> 4) * tpr;
    for (int tile = blockIdx.x; tile < tiles; tile += NBLK) {
        int mb = tile / tpr, nb = tile - mb * tpr;
        int row = mb * 16 + ty, col = nb * 16 + tx;
        const float* Arow = A + row * K + tx;
        const float* Wcol = W + ty * N + col;
        float ra[3], rw[3];
#pragma unroll
        for (int j = 0; j < 3; j++) {
            ra[j] = 0.f; rw[j] = 0.f;
            if (j < nk) { int k0 = (kbeg + j) << 4;
                          ra[j] = __ldcg(&Arow[k0]); rw[j] = __ldcg(&Wcol[(long)k0 * N]); }
        }
        u64 acc2 = 0ull;
        for (int i = 0; i < Kt0; i++) {
            int s = (kh << 2) | (i & 3);
            bool ok = i < nk;
            if (ok) { As[s][ty][tx] = ra[0]; Wt[s][tx][ty] = rw[0]; }
            ra[0] = ra[1]; ra[1] = ra[2];
            rw[0] = rw[1]; rw[1] = rw[2];
            if (i + 3 < nk) { int k0 = (kbeg + i + 3) << 4;
                              ra[2] = __ldcg(&Arow[k0]); rw[2] = __ldcg(&Wcol[(long)k0 * N]); }
            __syncthreads();
            if (ok) {
                const u64* a2 = (const u64*)As[s][ty];
                const u64* w2 = (const u64*)Wt[s][tx];
#pragma unroll
                for (int j = 0; j < 8; j++)
                    F32X2_FMA(acc2, a2[j], w2[j], acc2);
            }
        }
        unsigned alo, ahi;
        UNPACK2(alo, ahi, acc2);
        float acc = __uint_as_float(alo) + __uint_as_float(ahi);
        if (kh == 1) Cpart[tid] = acc;
        __syncthreads();
        if (kh == 0) {
            acc += Cpart[tid] + bias[col];
            if (ACT == 1) {
                acc = (acc >= 0.f) ? acc : 0.2f * acc;
            } else if (ACT == 2) {
                const float sc = 1.0507009873554805f, al = 1.6732632423543772f;
                acc = (acc > 0.f) ? sc * acc : sc * al * expm1f(acc);
            }
            C[row * N + col] = acc;
        }
        __syncthreads();
    }
}

// ---- 4-stage single-tile 16x32 GEMM phase, one output per thread.
// Requires (BB/16)*(N/32) == NBLK tiles exactly and K % 32 == 0.
template<int ACT>
__device__ void gemm32_phase(const float* __restrict__ A, const float* __restrict__ W,
                             const float* __restrict__ bias, float* __restrict__ C,
                             int N, int K, float* sm) {
    float (*As)[16][32] = (float(*)[16][32])sm;           // [4][16][32] = 2048
    float (*Wt)[32][34] = (float(*)[32][34])(sm + 2048);  // [4][32][34] = 4352
    int t = threadIdx.x;
    int tx = t & 31, ty = t >> 5;    // ty 0..15
    int tpr = N >> 5;
    int tile = blockIdx.x;
    int mb = tile / tpr, nb = tile - mb * tpr;
    int row = mb * 16 + ty, col = nb * 32 + tx;
    const float* Arow = A + row * K + tx;
    const float* W0 = W + col;
    int KT = K >> 5;
    float ra[3], rwa[3], rwb[3];
#pragma unroll
    for (int j = 0; j < 3; j++) {
        ra[j] = 0.f; rwa[j] = 0.f; rwb[j] = 0.f;
        if (j < KT) { int k0 = j << 5;
                      ra[j]  = __ldcg(&Arow[k0]);
                      rwa[j] = __ldcg(&W0[(long)(k0 + ty) * N]);
                      rwb[j] = __ldcg(&W0[(long)(k0 + 16 + ty) * N]); }
    }
    u64 acc2 = 0ull;
    for (int i = 0; i < KT; i++) {
        int s = i & 3;
        As[s][ty][tx]      = ra[0];
        Wt[s][tx][ty]      = rwa[0];
        Wt[s][tx][ty + 16] = rwb[0];
        ra[0] = ra[1]; ra[1] = ra[2];
        rwa[0] = rwa[1]; rwa[1] = rwa[2];
        rwb[0] = rwb[1]; rwb[1] = rwb[2];
        if (i + 3 < KT) {
            int k0 = (i + 3) << 5;
            ra[2]  = __ldcg(&Arow[k0]);
            rwa[2] = __ldcg(&W0[(long)(k0 + ty) * N]);
            rwb[2] = __ldcg(&W0[(long)(k0 + 16 + ty) * N]);
        }
        __syncthreads();
        const u64* a2 = (const u64*)As[s][ty];   // warp-broadcast reads
        const u64* w2 = (const u64*)Wt[s][tx];   // contiguous, 8B-aligned
#pragma unroll
        for (int j = 0; j < 16; j++)
            F32X2_FMA(acc2, a2[j], w2[j], acc2);
    }
    unsigned alo, ahi;
    UNPACK2(alo, ahi, acc2);
    float acc = __uint_as_float(alo) + __uint_as_float(ahi) + bias[col];
    if (ACT == 1) {
        acc = (acc >= 0.f) ? acc : 0.2f * acc;
    } else if (ACT == 2) {
        const float sc = 1.0507009873554805f, al = 1.6732632423543772f;
        acc = (acc > 0.f) ? sc * acc : sc * al * expm1f(acc);
    }
    C[row * N + col] = acc;
}

__global__ void __launch_bounds__(NTHR, 1)
mega_kernel(const float* __restrict__ x,    const float* __restrict__ eps,
            const float* __restrict__ e_w1, const float* __restrict__ e_b1,
            const float* __restrict__ e_w2, const float* __restrict__ e_b2,
            const float* __restrict__ w_mu, const float* __restrict__ b_mu,
            const float* __restrict__ w_lv, const float* __restrict__ b_lv,
            const float* __restrict__ d_w1, const float* __restrict__ d_b1,
            const float* __restrict__ d_w2, const float* __restrict__ d_b2,
            const float* __restrict__ p_w,  const float* __restrict__ p_b,
            const float* __restrict__ wd_w, const float* __restrict__ wd_b,
            const float* __restrict__ a_w,  const float* __restrict__ a_b,
            float* __restrict__ out) {
    __shared__ __align__(16) float sm[7168];
    int t = threadIdx.x;

    // P0: enc1 [128,784]@[784,256] leaky (128 tiles: 1 per CTA)
    gemm_phase<1>(x, e_w1, e_b1, g_h1, 256, 784, sm);
    grid_sync();
    // P1: enc2 [128,256]@[256,256] leaky
    gemm_phase<1>(g_h1, e_w2, e_b2, g_h2, 256, 256, sm);
    grid_sync();
    // P2: mu + logvar + z fused, 4-stage pipeline
    {
        float (*As)[16][16] = (float(*)[16][16])sm;            // [8][16][16] 2048
        float (*Wmt)[16][18] = (float(*)[16][18])(sm + 2048);  // [8][16][18] 2304
        float (*Wlt)[16][18] = (float(*)[16][18])(sm + 4352);  // [8][16][18] 2304
        float* Cm = sm + 6656;  // 256
        float* Cv = sm + 6912;  // 256
        int kh = t >> 8, tid = t & 255;
        int tx = tid & 15, ty = tid >> 4;
        const int NK = 8;       // 16 k-tiles, 8 per half
        for (int tile = blockIdx.x; tile < 32; tile += NBLK) {
            int mb = tile >> 2, nb = tile & 3;
            int row = mb * 16 + ty, col = nb * 16 + tx;
            const float* Arow = g_h2 + row * 256 + tx;
            const float* Wmc = w_mu + ty * 64 + col;
            const float* Wlc = w_lv + ty * 64 + col;
            int kb = kh * NK;
            float ra[3], rm[3], rl[3];
#pragma unroll
            for (int j = 0; j < 3; j++) {
                int k0 = (kb + j) << 4;   // NK=8 >= 3, always valid
                ra[j] = __ldcg(&Arow[k0]);
                rm[j] = __ldcg(&Wmc[k0 * 64]);
                rl[j] = __ldcg(&Wlc[k0 * 64]);
            }
            u64 am2 = 0ull, av2 = 0ull;
            for (int i = 0; i < NK; i++) {
                int s = (kh << 2) | (i & 3);
                As[s][ty][tx] = ra[0]; Wmt[s][tx][ty] = rm[0]; Wlt[s][tx][ty] = rl[0];
                ra[0] = ra[1]; ra[1] = ra[2];
                rm[0] = rm[1]; rm[1] = rm[2];
                rl[0] = rl[1]; rl[1] = rl[2];
                if (i + 3 < NK) { int k0 = (kb + i + 3) << 4;
                                  ra[2] = __ldcg(&Arow[k0]);
                                  rm[2] = __ldcg(&Wmc[k0 * 64]);
                                  rl[2] = __ldcg(&Wlc[k0 * 64]); }
                __syncthreads();
                const u64* a2 = (const u64*)As[s][ty];
                const u64* m2 = (const u64*)Wmt[s][tx];
                const u64* l2 = (const u64*)Wlt[s][tx];
#pragma unroll
                for (int j = 0; j < 8; j++) {
                    u64 av_ = a2[j];
                    F32X2_FMA(am2, av_, m2[j], am2);
                    F32X2_FMA(av2, av_, l2[j], av2);
                }
            }
            unsigned lo, hi;
            UNPACK2(lo, hi, am2);
            float am = __uint_as_float(lo) + __uint_as_float(hi);
            UNPACK2(lo, hi, av2);
            float av = __uint_as_float(lo) + __uint_as_float(hi);
            if (kh == 1) { Cm[tid] = am; Cv[tid] = av; }
            __syncthreads();
            if (kh == 0) {
                am += Cm[tid] + b_mu[col];
                av += Cv[tid] + b_lv[col];
                out[OFF_MU + row * 64 + col] = am;
                out[OFF_LV + row * 64 + col] = av;
                g_z[row * 64 + col] = am + eps[row * 64 + col] * expf(0.5f * av);
            }
            __syncthreads();
        }
    }
    grid_sync();
    // P3: dec1 [128,64]@[64,512] selu — single tile per CTA
    gemm32_phase<2>(g_z, d_w1, d_b1, g_dh1, 512, 64, sm);
    grid_sync();
    // P4: dec2 [128,512]@[512,512] selu — single tile per CTA
    gemm32_phase<2>(g_dh1, d_w2, d_b2, g_dh2, 512, 512, sm);
    grid_sync();
    // P5: heads + bezier + render, one CTA per batch element
    {
        int b = blockIdx.x;
        float* h   = sm;        // 512
        float* pts = sm + 512;  // 40
        float* wa  = sm + 552;  // 4
        float* cu4f = sm + 560; // 384 floats = [2][48] float4, 16B-aligned
        h[t] = __ldcg(&g_dh2[b * HIDDEN + t]);
        __syncthreads();
        // heads: warp per output, shfl reduce
        {
            int wid = t >> 5, lane = t & 31;
            for (int o = wid; o < 40; o += 16) {
                float acc = 0.f;
#pragma unroll
                for (int k = lane; k < HIDDEN; k += 32)
                    acc = fmaf(h[k], __ldg(&p_w[k * 40 + o]), acc);
#pragma unroll
                for (int off = 16; off; off >>= 1)
                    acc += __shfl_down_sync(0xffffffffu, acc, off);
                if (lane == 0) pts[o] = tanhf(acc + p_b[o]) * 12.f + 14.f;
            }
            if (wid >= 8 && wid < 10) {          // widths
                int j = wid - 8;
                float acc = 0.f;
#pragma unroll
                for (int k = lane; k < HIDDEN; k += 32)
                    acc = fmaf(h[k], __ldg(&wd_w[k * 2 + j]), acc);
#pragma unroll
                for (int off = 16; off; off >>= 1)
                    acc += __shfl_down_sync(0xffffffffu, acc, off);
                if (lane == 0) wa[j] = 2.f / (1.f + __expf(-(acc + wd_b[j]))) + 1.f;
            }
            if (wid >= 10 && wid < 12) {         // alphas
                int j = wid - 10;
                float acc = 0.f;
#pragma unroll
                for (int k = lane; k < HIDDEN; k += 32)
                    acc = fmaf(h[k], __ldg(&a_w[k * 2 + j]), acc);
#pragma unroll
                for (int off = 16; off; off >>= 1)
                    acc += __shfl_down_sync(0xffffffffu, acc, off);
                if (lane == 0) wa[2 + j] = 1.f / (1.f + __expf(-(acc + a_b[j])));
            }
        }
        __syncthreads();
        // cp out: [P,S,4,2] overlapping segments
        if (t < 48) {
            int p = t / 24, rem = t % 24;
            int s = rem / 8, kc = rem % 8;
            int k = kc / 2, c = kc & 1;
            out[OFF_CP + b * 48 + t] = pts[p * 20 + (3 * s + k) * 2 + c];
        }
        if (t < 2)            out[OFF_W + b * 2 + t] = wa[t];
        if (t >= 2 && t < 4)  out[OFF_A + b * 2 + (t - 2)] = wa[t];
        // curve samples into interleaved float4 quads (x2i, x2i+1, y2i, y2i+1)
        if (t < NPATH * MPTS * 2) {
            int i = t;
            int p = i / (MPTS * 2);
            int m = (i >> 1) % MPTS;
            int c = i & 1;
            int s = m / TSAMP, tt = m % TSAMP;
            float tv = ((float)tt + 0.5f) / (float)TSAMP;
            float u = 1.f - tv;
            float b0 = u * u * u;
            float b1 = 3.f * tv * u * u;
            float b2 = 3.f * tv * tv * u;
            float b3 = tv * tv * tv;
            const float* Pp = &pts[p * 20 + (3 * s) * 2 + c];
            float v = b0 * Pp[0] + b1 * Pp[2] + b2 * Pp[4] + b3 * Pp[6];
            cu4f[(p * 48 + (m >> 1)) * 4 + ((c << 1) | (m & 1))] = v;
        }
        __syncthreads();
        // rasterizer: packed f32x2, 2 curve points via 1 LDS.128, 4 subsamples
        for (int pix = t; pix < 784; pix += NTHR) {
            int py = pix / 28, px = pix % 28;
            float x0 = (float)px + 0.25f, x1 = (float)px + 0.75f;
            float y0 = (float)py + 0.25f, y1 = (float)py + 0.75f;
            float nx0 = -x0, nx1 = -x1, ny0 = -y0, ny1 = -y1;
            u64 nx0p, nx1p, ny0p, ny1p;
            PACK2(nx0p, __float_as_uint(nx0), __float_as_uint(nx0));
            PACK2(nx1p, __float_as_uint(nx1), __float_as_uint(nx1));
            PACK2(ny0p, __float_as_uint(ny0), __float_as_uint(ny0));
            PACK2(ny1p, __float_as_uint(ny1), __float_as_uint(ny1));
            float v00 = 1.f, v01 = 1.f, v10 = 1.f, v11 = 1.f;
#pragma unroll
            for (int p = 0; p < NPATH; p++) {
                const float4* q4 = (const float4*)cu4f + p * 48;
                float m00 = 1e30f, m01 = 1e30f, m10 = 1e30f, m11 = 1e30f;
#pragma unroll 8
                for (int i = 0; i < MPTS / 2; i++) {
                    float4 q = q4[i];
                    u64 cxp, cyp;
                    PACK2(cxp, __float_as_uint(q.x), __float_as_uint(q.y));
                    PACK2(cyp, __float_as_uint(q.z), __float_as_uint(q.w));
                    u64 dx0, dx1, dy0, dy1, sy0, sy1;
                    u64 s00, s01, s10, s11;
                    F32X2_ADD(dx0, cxp, nx0p);
                    F32X2_ADD(dx1, cxp, nx1p);
                    F32X2_ADD(dy0, cyp, ny0p);
                    F32X2_ADD(dy1, cyp, ny1p);
                    F32X2_MUL(sy0, dy0, dy0);
                    F32X2_MUL(sy1, dy1, dy1);
                    F32X2_FMA(s00, dx0, dx0, sy0);
                    F32X2_FMA(s01, dx1, dx1, sy0);
                    F32X2_FMA(s10, dx0, dx0, sy1);
                    F32X2_FMA(s11, dx1, dx1, sy1);
                    unsigned lo, hi;
                    UNPACK2(lo, hi, s00);
                    m00 = fminf(m00, __uint_as_float(lo));
                    m00 = fminf(m00, __uint_as_float(hi));
                    UNPACK2(lo, hi, s01);
                    m01 = fminf(m01, __uint_as_float(lo));
                    m01 = fminf(m01, __uint_as_float(hi));
                    UNPACK2(lo, hi, s10);
                    m10 = fminf(m10, __uint_as_float(lo));
                    m10 = fminf(m10, __uint_as_float(hi));
                    UNPACK2(lo, hi, s11);
                    m11 = fminf(m11, __uint_as_float(lo));
                    m11 = fminf(m11, __uint_as_float(hi));
                }
                float w = wa[p] * 0.5f;
                float al = wa[2 + p];
                float t00 = m00 + 1e-12f, t01 = m01 + 1e-12f;
                float t10 = m10 + 1e-12f, t11 = m11 + 1e-12f;
                float d00 = t00 * rsqrtf(t00);
                float d01 = t01 * rsqrtf(t01);
                float d10 = t10 * rsqrtf(t10);
                float d11 = t11 * rsqrtf(t11);
                v00 *= 1.f - __fdividef(al, 1.f + __expf((d00 - w) * 2.f));
                v01 *= 1.f - __fdividef(al, 1.f + __expf((d01 - w) * 2.f));
                v10 *= 1.f - __fdividef(al, 1.f + __expf((d10 - w) * 2.f));
                v11 *= 1.f - __fdividef(al, 1.f + __expf((d11 - w) * 2.f));
            }
            out[OFF_REND + b * 784 + pix] = 1.f - 0.25f * (v00 + v01 + v10 + v11);
        }
    }
}

extern "C" void kernel_launch(void* const* d_in, const int* in_sizes, int n_in,
                              void* d_out, int out_size) {
    const float* x    = (const float*)d_in[0];
    const float* eps  = (const float*)d_in[1];
    const float* e_w1 = (const float*)d_in[2];
    const float* e_b1 = (const float*)d_in[3];
    const float* e_w2 = (const float*)d_in[4];
    const float* e_b2 = (const float*)d_in[5];
    const float* w_mu = (const float*)d_in[6];
    const float* b_mu = (const float*)d_in[7];
    const float* w_lv = (const float*)d_in[8];
    const float* b_lv = (const float*)d_in[9];
    const float* d_w1 = (const float*)d_in[10];
    const float* d_b1 = (const float*)d_in[11];
    const float* d_w2 = (const float*)d_in[12];
    const float* d_b2 = (const float*)d_in[13];
    const float* p_w  = (const float*)d_in[14];
    const float* p_b  = (const float*)d_in[15];
    const float* wd_w = (const float*)d_in[16];
    const float* wd_b = (const float*)d_in[17];
    const float* a_w  = (const float*)d_in[18];
    const float* a_b  = (const float*)d_in[19];
    float* out = (float*)d_out;

    mega_kernel<<<NBLK, NTHR>>>(x, eps, e_w1, e_b1, e_w2, e_b2, w_mu, b_mu,
                                w_lv, b_lv, d_w1, d_b1, d_w2, d_b2,
                                p_w, p_b, wd_w, wd_b, a_w, a_b, out);
}

// round 14
// speedup vs baseline: 2.1896x; 1.0419x over previous
#include <cuda_runtime.h>
#include <math.h>

#define BB 128
#define NBLK 128
#define NTHR 512
#define LATENT 64
#define HIDDEN 512
#define NPATH 2
#define SEG 3
#define TSAMP 32
#define MPTS (SEG*TSAMP) // 96

// output offsets (floats), concat in return order
#define OFF_REND 0
#define OFF_MU   (BB*784)
#define OFF_LV   (OFF_MU + BB*64)
#define OFF_CP   (OFF_LV + BB*64)
#define OFF_W    (OFF_CP + BB*48)
#define OFF_A    (OFF_W + BB*2)

// packed fp32x2 (Blackwell)
#define F32X2_ADD(o,a,b)   asm("add.rn.f32x2 %0,%1,%2;" : "=l"(o) : "l"(a), "l"(b))
#define F32X2_MUL(o,a,b)   asm("mul.rn.f32x2 %0,%1,%2;" : "=l"(o) : "l"(a), "l"(b))
#define F32X2_FMA(o,a,b,c) asm("fma.rn.f32x2 %0,%1,%2,%3;" : "=l"(o) : "l"(a), "l"(b), "l"(c))
#define PACK2(o,lo,hi)     asm("mov.b64 %0,{%1,%2};" : "=l"(o) : "r"(lo), "r"(hi))
#define UNPACK2(lo,hi,i)   asm("mov.b64 {%0,%1},%2;" : "=r"(lo), "=r"(hi) : "l"(i))

typedef unsigned long long u64;

// scratch (inter-phase activations)
__device__ float g_h1[BB*256];
__device__ float g_h2[BB*256];
__device__ float g_z[BB*LATENT];
__device__ float g_dh1[BB*HIDDEN];
__device__ float g_dh2[BB*HIDDEN];
__device__ unsigned g_cnt;
__device__ unsigned g_gen;

__device__ __forceinline__ void grid_sync() {
    __syncthreads();
    if (threadIdx.x == 0) {
        __threadfence();
        volatile unsigned* vgen = &g_gen;
        unsigned gen = *vgen;
        if (atomicAdd(&g_cnt, 1u) == NBLK - 1) {
            g_cnt = 0;
            __threadfence();
            atomicAdd(&g_gen, 1u);
        } else {
            while (*vgen == gen) { __nanosleep(32); }
        }
    }
    __syncthreads();
}

// ---- 4-stage pipelined tiled GEMM phase, 512 threads, K split 2 halves.
template<int ACT>
__device__ void gemm_phase(const float* __restrict__ A, const float* __restrict__ W,
                           const float* __restrict__ bias, float* __restrict__ C,
                           int N, int K, float* sm) {
    float (*As)[16][16] = (float(*)[16][16])sm;           // [8][16][16] = 2048
    float (*Wt)[16][18] = (float(*)[16][18])(sm + 2048);  // [8][16][18] = 2304
    float* Cpart = sm + 4352;                             // 256
    int t = threadIdx.x;
    int kh = t >> 8, tid = t & 255;
    int tx = tid & 15, ty = tid >> 4;
    int Kt = K >> 4;
    int Kt0 = (Kt + 1) >> 1;
    int kbeg = kh ? Kt0 : 0;
    int nk = kh ? (Kt - Kt0) : Kt0;
    int tpr = N >> 4;
    int tiles = (BB >> 4) * tpr;
    for (int tile = blockIdx.x; tile < tiles; tile += NBLK) {
        int mb = tile / tpr, nb = tile - mb * tpr;
        int row = mb * 16 + ty, col = nb * 16 + tx;
        const float* Arow = A + row * K + tx;
        const float* Wcol = W + ty * N + col;
        float ra[3], rw[3];
#pragma unroll
        for (int j = 0; j < 3; j++) {
            ra[j] = 0.f; rw[j] = 0.f;
            if (j < nk) { int k0 = (kbeg + j) << 4;
                          ra[j] = __ldcg(&Arow[k0]); rw[j] = __ldcg(&Wcol[(long)k0 * N]); }
        }
        u64 acc2 = 0ull;
        for (int i = 0; i < Kt0; i++) {
            int s = (kh << 2) | (i & 3);
            bool ok = i < nk;
            if (ok) { As[s][ty][tx] = ra[0]; Wt[s][tx][ty] = rw[0]; }
            ra[0] = ra[1]; ra[1] = ra[2];
            rw[0] = rw[1]; rw[1] = rw[2];
            if (i + 3 < nk) { int k0 = (kbeg + i + 3) << 4;
                              ra[2] = __ldcg(&Arow[k0]); rw[2] = __ldcg(&Wcol[(long)k0 * N]); }
            __syncthreads();
            if (ok) {
                const u64* a2 = (const u64*)As[s][ty];
                const u64* w2 = (const u64*)Wt[s][tx];
#pragma unroll
                for (int j = 0; j < 8; j++)
                    F32X2_FMA(acc2, a2[j], w2[j], acc2);
            }
        }
        unsigned alo, ahi;
        UNPACK2(alo, ahi, acc2);
        float acc = __uint_as_float(alo) + __uint_as_float(ahi);
        if (kh == 1) Cpart[tid] = acc;
        __syncthreads();
        if (kh == 0) {
            acc += Cpart[tid] + bias[col];
            if (ACT == 1) {
                acc = (acc >= 0.f) ? acc : 0.2f * acc;
            } else if (ACT == 2) {
                const float sc = 1.0507009873554805f, al = 1.6732632423543772f;
                acc = (acc > 0.f) ? sc * acc : sc * al * expm1f(acc);
            }
            C[row * N + col] = acc;
        }
        __syncthreads();
    }
}

// ---- 4-stage single-tile 16x32 GEMM phase, one output per thread.
template<int ACT>
__device__ void gemm32_phase(const float* __restrict__ A, const float* __restrict__ W,
                             const float* __restrict__ bias, float* __restrict__ C,
                             int N, int K, float* sm) {
    float (*As)[16][32] = (float(*)[16][32])sm;           // [4][16][32] = 2048
    float (*Wt)[32][34] = (float(*)[32][34])(sm + 2048);  // [4][32][34] = 4352
    int t = threadIdx.x;
    int tx = t & 31, ty = t >> 5;
    int tpr = N >> 5;
    int tile = blockIdx.x;
    int mb = tile / tpr, nb = tile - mb * tpr;
    int row = mb * 16 + ty, col = nb * 32 + tx;
    const float* Arow = A + row * K + tx;
    const float* W0 = W + col;
    int KT = K >> 5;
    float ra[3], rwa[3], rwb[3];
#pragma unroll
    for (int j = 0; j < 3; j++) {
        ra[j] = 0.f; rwa[j] = 0.f; rwb[j] = 0.f;
        if (j < KT) { int k0 = j << 5;
                      ra[j]  = __ldcg(&Arow[k0]);
                      rwa[j] = __ldcg(&W0[(long)(k0 + ty) * N]);
                      rwb[j] = __ldcg(&W0[(long)(k0 + 16 + ty) * N]); }
    }
    u64 acc2 = 0ull;
    for (int i = 0; i < KT; i++) {
        int s = i & 3;
        As[s][ty][tx]      = ra[0];
        Wt[s][tx][ty]      = rwa[0];
        Wt[s][tx][ty + 16] = rwb[0];
        ra[0] = ra[1]; ra[1] = ra[2];
        rwa[0] = rwa[1]; rwa[1] = rwa[2];
        rwb[0] = rwb[1]; rwb[1] = rwb[2];
        if (i + 3 < KT) {
            int k0 = (i + 3) << 5;
            ra[2]  = __ldcg(&Arow[k0]);
            rwa[2] = __ldcg(&W0[(long)(k0 + ty) * N]);
            rwb[2] = __ldcg(&W0[(long)(k0 + 16 + ty) * N]);
        }
        __syncthreads();
        const u64* a2 = (const u64*)As[s][ty];
        const u64* w2 = (const u64*)Wt[s][tx];
#pragma unroll
        for (int j = 0; j < 16; j++)
            F32X2_FMA(acc2, a2[j], w2[j], acc2);
    }
    unsigned alo, ahi;
    UNPACK2(alo, ahi, acc2);
    float acc = __uint_as_float(alo) + __uint_as_float(ahi) + bias[col];
    if (ACT == 1) {
        acc = (acc >= 0.f) ? acc : 0.2f * acc;
    } else if (ACT == 2) {
        const float sc = 1.0507009873554805f, al = 1.6732632423543772f;
        acc = (acc > 0.f) ? sc * acc : sc * al * expm1f(acc);
    }
    C[row * N + col] = acc;
}

__global__ void __launch_bounds__(NTHR, 1)
mega_kernel(const float* __restrict__ x,    const float* __restrict__ eps,
            const float* __restrict__ e_w1, const float* __restrict__ e_b1,
            const float* __restrict__ e_w2, const float* __restrict__ e_b2,
            const float* __restrict__ w_mu, const float* __restrict__ b_mu,
            const float* __restrict__ w_lv, const float* __restrict__ b_lv,
            const float* __restrict__ d_w1, const float* __restrict__ d_b1,
            const float* __restrict__ d_w2, const float* __restrict__ d_b2,
            const float* __restrict__ p_w,  const float* __restrict__ p_b,
            const float* __restrict__ wd_w, const float* __restrict__ wd_b,
            const float* __restrict__ a_w,  const float* __restrict__ a_b,
            float* __restrict__ out) {
    __shared__ __align__(16) float sm[7168];
    int t = threadIdx.x;

    // P0: enc1 [128,784]@[784,256] leaky
    gemm_phase<1>(x, e_w1, e_b1, g_h1, 256, 784, sm);
    grid_sync();
    // P1: enc2 [128,256]@[256,256] leaky
    gemm_phase<1>(g_h1, e_w2, e_b2, g_h2, 256, 256, sm);
    grid_sync();
    // P2: mu + logvar + z fused, 4-stage pipeline
    {
        float (*As)[16][16] = (float(*)[16][16])sm;            // [8][16][16] 2048
        float (*Wmt)[16][18] = (float(*)[16][18])(sm + 2048);  // [8][16][18] 2304
        float (*Wlt)[16][18] = (float(*)[16][18])(sm + 4352);  // [8][16][18] 2304
        float* Cm = sm + 6656;
        float* Cv = sm + 6912;
        int kh = t >> 8, tid = t & 255;
        int tx = tid & 15, ty = tid >> 4;
        const int NK = 8;
        for (int tile = blockIdx.x; tile < 32; tile += NBLK) {
            int mb = tile >> 2, nb = tile & 3;
            int row = mb * 16 + ty, col = nb * 16 + tx;
            const float* Arow = g_h2 + row * 256 + tx;
            const float* Wmc = w_mu + ty * 64 + col;
            const float* Wlc = w_lv + ty * 64 + col;
            int kb = kh * NK;
            float ra[3], rm[3], rl[3];
#pragma unroll
            for (int j = 0; j < 3; j++) {
                int k0 = (kb + j) << 4;
                ra[j] = __ldcg(&Arow[k0]);
                rm[j] = __ldcg(&Wmc[k0 * 64]);
                rl[j] = __ldcg(&Wlc[k0 * 64]);
            }
            u64 am2 = 0ull, av2 = 0ull;
            for (int i = 0; i < NK; i++) {
                int s = (kh << 2) | (i & 3);
                As[s][ty][tx] = ra[0]; Wmt[s][tx][ty] = rm[0]; Wlt[s][tx][ty] = rl[0];
                ra[0] = ra[1]; ra[1] = ra[2];
                rm[0] = rm[1]; rm[1] = rm[2];
                rl[0] = rl[1]; rl[1] = rl[2];
                if (i + 3 < NK) { int k0 = (kb + i + 3) << 4;
                                  ra[2] = __ldcg(&Arow[k0]);
                                  rm[2] = __ldcg(&Wmc[k0 * 64]);
                                  rl[2] = __ldcg(&Wlc[k0 * 64]); }
                __syncthreads();
                const u64* a2 = (const u64*)As[s][ty];
                const u64* m2 = (const u64*)Wmt[s][tx];
                const u64* l2 = (const u64*)Wlt[s][tx];
#pragma unroll
                for (int j = 0; j < 8; j++) {
                    u64 av_ = a2[j];
                    F32X2_FMA(am2, av_, m2[j], am2);
                    F32X2_FMA(av2, av_, l2[j], av2);
                }
            }
            unsigned lo, hi;
            UNPACK2(lo, hi, am2);
            float am = __uint_as_float(lo) + __uint_as_float(hi);
            UNPACK2(lo, hi, av2);
            float av = __uint_as_float(lo) + __uint_as_float(hi);
            if (kh == 1) { Cm[tid] = am; Cv[tid] = av; }
            __syncthreads();
            if (kh == 0) {
                am += Cm[tid] + b_mu[col];
                av += Cv[tid] + b_lv[col];
                out[OFF_MU + row * 64 + col] = am;
                out[OFF_LV + row * 64 + col] = av;
                g_z[row * 64 + col] = am + eps[row * 64 + col] * expf(0.5f * av);
            }
            __syncthreads();
        }
    }
    grid_sync();
    // P3: dec1 [128,64]@[64,512] selu
    gemm32_phase<2>(g_z, d_w1, d_b1, g_dh1, 512, 64, sm);
    grid_sync();
    // P4: dec2 [128,512]@[512,512] selu
    gemm32_phase<2>(g_dh1, d_w2, d_b2, g_dh2, 512, 512, sm);
    grid_sync();
    // P5: heads + bezier + render, one CTA per batch element
    {
        int b = blockIdx.x;
        float* h    = sm;        // 512
        float* pts  = sm + 512;  // 40
        float* wa   = sm + 552;  // 4
        float* cu4f = sm + 560;  // 384 floats = [2][48] float4, 16B-aligned
        float* part = sm + 944;  // 352 partials (8 groups x 44 outputs)
        h[t] = __ldcg(&g_dh2[b * HIDDEN + t]);
        __syncthreads();
        // heads: 8 k-groups x 44 outputs; coalesced weight loads (consecutive
        // threads -> consecutive output columns -> consecutive addresses)
        if (t < 352) {
            int g = t / 44, o = t - g * 44;
            const float* Wp; int stride;
            if (o < 40)      { Wp = p_w + o;         stride = 40; }
            else if (o < 42) { Wp = wd_w + (o - 40); stride = 2;  }
            else             { Wp = a_w + (o - 42);  stride = 2;  }
            int kb = g * 64;
            const float* Wk = Wp + (long)kb * stride;
            float acc = 0.f;
#pragma unroll 8
            for (int i = 0; i < 64; i++)
                acc = fmaf(h[kb + i], __ldg(&Wk[i * stride]), acc);
            part[t] = acc;
        }
        __syncthreads();
        if (t < 44) {
            float acc = 0.f;
#pragma unroll
            for (int g = 0; g < 8; g++) acc += part[g * 44 + t];
            if (t < 40)      pts[t] = tanhf(acc + p_b[t]) * 12.f + 14.f;
            else if (t < 42) wa[t - 40] = 2.f / (1.f + __expf(-(acc + wd_b[t - 40]))) + 1.f;
            else             wa[t - 40] = 1.f / (1.f + __expf(-(acc + a_b[t - 42])));
        }
        __syncthreads();
        // cp out: [P,S,4,2] overlapping segments
        if (t < 48) {
            int p = t / 24, rem = t % 24;
            int s = rem / 8, kc = rem % 8;
            int k = kc / 2, c = kc & 1;
            out[OFF_CP + b * 48 + t] = pts[p * 20 + (3 * s + k) * 2 + c];
        }
        if (t < 2)            out[OFF_W + b * 2 + t] = wa[t];
        if (t >= 2 && t < 4)  out[OFF_A + b * 2 + (t - 2)] = wa[t];
        // curve samples into interleaved float4 quads (x2i, x2i+1, y2i, y2i+1)
        if (t < NPATH * MPTS * 2) {
            int i = t;
            int p = i / (MPTS * 2);
            int m = (i >> 1) % MPTS;
            int c = i & 1;
            int s = m / TSAMP, tt = m % TSAMP;
            float tv = ((float)tt + 0.5f) / (float)TSAMP;
            float u = 1.f - tv;
            float b0 = u * u * u;
            float b1 = 3.f * tv * u * u;
            float b2 = 3.f * tv * tv * u;
            float b3 = tv * tv * tv;
            const float* Pp = &pts[p * 20 + (3 * s) * 2 + c];
            float v = b0 * Pp[0] + b1 * Pp[2] + b2 * Pp[4] + b3 * Pp[6];
            cu4f[(p * 48 + (m >> 1)) * 4 + ((c << 1) | (m & 1))] = v;
        }
        __syncthreads();
        // rasterizer: both paths interleaved (8 independent min-chains)
        for (int pix = t; pix < 784; pix += NTHR) {
            int py = pix / 28, px = pix % 28;
            float x0 = (float)px + 0.25f, x1 = (float)px + 0.75f;
            float y0 = (float)py + 0.25f, y1 = (float)py + 0.75f;
            float nx0 = -x0, nx1 = -x1, ny0 = -y0, ny1 = -y1;
            u64 nx0p, nx1p, ny0p, ny1p;
            PACK2(nx0p, __float_as_uint(nx0), __float_as_uint(nx0));
            PACK2(nx1p, __float_as_uint(nx1), __float_as_uint(nx1));
            PACK2(ny0p, __float_as_uint(ny0), __float_as_uint(ny0));
            PACK2(ny1p, __float_as_uint(ny1), __float_as_uint(ny1));
            const float4* q4 = (const float4*)cu4f;
            float a00 = 1e30f, a01 = 1e30f, a10 = 1e30f, a11 = 1e30f;
            float b00 = 1e30f, b01 = 1e30f, b10 = 1e30f, b11 = 1e30f;
#pragma unroll 4
            for (int i = 0; i < MPTS / 2; i++) {
                float4 qa = q4[i];
                float4 qb = q4[48 + i];
                u64 cxa, cya, cxb, cyb;
                PACK2(cxa, __float_as_uint(qa.x), __float_as_uint(qa.y));
                PACK2(cya, __float_as_uint(qa.z), __float_as_uint(qa.w));
                PACK2(cxb, __float_as_uint(qb.x), __float_as_uint(qb.y));
                PACK2(cyb, __float_as_uint(qb.z), __float_as_uint(qb.w));
                u64 dx0, dx1, dy0, dy1, sy0, sy1, s00, s01, s10, s11;
                unsigned lo, hi;
                // path 0
                F32X2_ADD(dx0, cxa, nx0p);
                F32X2_ADD(dx1, cxa, nx1p);
                F32X2_ADD(dy0, cya, ny0p);
                F32X2_ADD(dy1, cya, ny1p);
                F32X2_MUL(sy0, dy0, dy0);
                F32X2_MUL(sy1, dy1, dy1);
                F32X2_FMA(s00, dx0, dx0, sy0);
                F32X2_FMA(s01, dx1, dx1, sy0);
                F32X2_FMA(s10, dx0, dx0, sy1);
                F32X2_FMA(s11, dx1, dx1, sy1);
                UNPACK2(lo, hi, s00);
                a00 = fminf(a00, __uint_as_float(lo)); a00 = fminf(a00, __uint_as_float(hi));
                UNPACK2(lo, hi, s01);
                a01 = fminf(a01, __uint_as_float(lo)); a01 = fminf(a01, __uint_as_float(hi));
                UNPACK2(lo, hi, s10);
                a10 = fminf(a10, __uint_as_float(lo)); a10 = fminf(a10, __uint_as_float(hi));
                UNPACK2(lo, hi, s11);
                a11 = fminf(a11, __uint_as_float(lo)); a11 = fminf(a11, __uint_as_float(hi));
                // path 1
                F32X2_ADD(dx0, cxb, nx0p);
                F32X2_ADD(dx1, cxb, nx1p);
                F32X2_ADD(dy0, cyb, ny0p);
                F32X2_ADD(dy1, cyb, ny1p);
                F32X2_MUL(sy0, dy0, dy0);
                F32X2_MUL(sy1, dy1, dy1);
                F32X2_FMA(s00, dx0, dx0, sy0);
                F32X2_FMA(s01, dx1, dx1, sy0);
                F32X2_FMA(s10, dx0, dx0, sy1);
                F32X2_FMA(s11, dx1, dx1, sy1);
                UNPACK2(lo, hi, s00);
                b00 = fminf(b00, __uint_as_float(lo)); b00 = fminf(b00, __uint_as_float(hi));
                UNPACK2(lo, hi, s01);
                b01 = fminf(b01, __uint_as_float(lo)); b01 = fminf(b01, __uint_as_float(hi));
                UNPACK2(lo, hi, s10);
                b10 = fminf(b10, __uint_as_float(lo)); b10 = fminf(b10, __uint_as_float(hi));
                UNPACK2(lo, hi, s11);
                b11 = fminf(b11, __uint_as_float(lo)); b11 = fminf(b11, __uint_as_float(hi));
            }
            float v00 = 1.f, v01 = 1.f, v10 = 1.f, v11 = 1.f;
#pragma unroll
            for (int p = 0; p < NPATH; p++) {
                float m00 = p ? b00 : a00, m01 = p ? b01 : a01;
                float m10 = p ? b10 : a10, m11 = p ? b11 : a11;
                float w = wa[p] * 0.5f;
                float al = wa[2 + p];
                float t00 = m00 + 1e-12f, t01 = m01 + 1e-12f;
                float t10 = m10 + 1e-12f, t11 = m11 + 1e-12f;
                float d00 = t00 * rsqrtf(t00);
                float d01 = t01 * rsqrtf(t01);
                float d10 = t10 * rsqrtf(t10);
                float d11 = t11 * rsqrtf(t11);
                v00 *= 1.f - __fdividef(al, 1.f + __expf((d00 - w) * 2.f));
                v01 *= 1.f - __fdividef(al, 1.f + __expf((d01 - w) * 2.f));
                v10 *= 1.f - __fdividef(al, 1.f + __expf((d10 - w) * 2.f));
                v11 *= 1.f - __fdividef(al, 1.f + __expf((d11 - w) * 2.f));
            }
            out[OFF_REND + b * 784 + pix] = 1.f - 0.25f * (v00 + v01 + v10 + v11);
        }
    }
}

extern "C" void kernel_launch(void* const* d_in, const int* in_sizes, int n_in,
                              void* d_out, int out_size) {
    const float* x    = (const float*)d_in[0];
    const float* eps  = (const float*)d_in[1];
    const float* e_w1 = (const float*)d_in[2];
    const float* e_b1 = (const float*)d_in[3];
    const float* e_w2 = (const float*)d_in[4];
    const float* e_b2 = (const float*)d_in[5];
    const float* w_mu = (const float*)d_in[6];
    const float* b_mu = (const float*)d_in[7];
    const float* w_lv = (const float*)d_in[8];
    const float* b_lv = (const float*)d_in[9];
    const float* d_w1 = (const float*)d_in[10];
    const float* d_b1 = (const float*)d_in[11];
    const float* d_w2 = (const float*)d_in[12];
    const float* d_b2 = (const float*)d_in[13];
    const float* p_w  = (const float*)d_in[14];
    const float* p_b  = (const float*)d_in[15];
    const float* wd_w = (const float*)d_in[16];
    const float* wd_b = (const float*)d_in[17];
    const float* a_w  = (const float*)d_in[18];
    const float* a_b  = (const float*)d_in[19];
    float* out = (float*)d_out;

    mega_kernel<<<NBLK, NTHR>>>(x, eps, e_w1, e_b1, e_w2, e_b2, w_mu, b_mu,
                                w_lv, b_lv, d_w1, d_b1, d_w2, d_b2,
                                p_w, p_b, wd_w, wd_b, a_w, a_b, out);
}